// round 7
// baseline (speedup 1.0000x reference)
#include <cuda_runtime.h>
#include <cuda_bf16.h>
#include <cstdint>
#include <math.h>

#define BB   16
#define SQL  2048
#define SKL  2048
#define DD   128
#define NROWS (BB * SQL)
#define NTILES 16

// ---------------- scratch (__device__ globals; no allocation) ----------------
__device__ __nv_bfloat16 g_Qh[(size_t)BB * SQL * DD];
__device__ __nv_bfloat16 g_Ql[(size_t)BB * SQL * DD];
__device__ __nv_bfloat16 g_Kh[(size_t)BB * SKL * DD];
__device__ __nv_bfloat16 g_Kl[(size_t)BB * SKL * DD];
__device__ __nv_bfloat16 g_Vth[(size_t)BB * DD * SKL];   // V^T: [b][dv][k]
__device__ __nv_bfloat16 g_Vtl[(size_t)BB * DD * SKL];
__device__ float g_ps[(size_t)NROWS * NTILES];           // per-(row,ktile) sum exp

// ---------------- helpers ----------------------------------------------------
__device__ __forceinline__ uint32_t pack2_hi(float a, float b, float& la, float& lb) {
    __nv_bfloat16 ha = __float2bfloat16_rn(a), hb = __float2bfloat16_rn(b);
    la = a - __bfloat162float(ha);
    lb = b - __bfloat162float(hb);
    return (uint32_t)__bfloat16_as_ushort(ha) | ((uint32_t)__bfloat16_as_ushort(hb) << 16);
}
__device__ __forceinline__ uint32_t pack2(float a, float b) {
    __nv_bfloat16 ha = __float2bfloat16_rn(a), hb = __float2bfloat16_rn(b);
    return (uint32_t)__bfloat16_as_ushort(ha) | ((uint32_t)__bfloat16_as_ushort(hb) << 16);
}
__device__ __forceinline__ void mma_bf16(float* c, uint32_t a0, uint32_t a1,
                                         uint32_t a2, uint32_t a3,
                                         uint32_t b0, uint32_t b1) {
    asm volatile(
        "mma.sync.aligned.m16n8k16.row.col.f32.bf16.bf16.f32 "
        "{%0,%1,%2,%3}, {%4,%5,%6,%7}, {%8,%9}, {%0,%1,%2,%3};"
        : "+f"(c[0]), "+f"(c[1]), "+f"(c[2]), "+f"(c[3])
        : "r"(a0), "r"(a1), "r"(a2), "r"(a3), "r"(b0), "r"(b1));
}
__device__ __forceinline__ void ldsm4(uint32_t& r0, uint32_t& r1, uint32_t& r2,
                                      uint32_t& r3, uint32_t addr) {
    asm volatile("ldmatrix.sync.aligned.m8n8.x4.shared.b16 {%0,%1,%2,%3}, [%4];"
                 : "=r"(r0), "=r"(r1), "=r"(r2), "=r"(r3) : "r"(addr));
}
__device__ __forceinline__ void cpa16(uint32_t dst, const void* src) {
    asm volatile("cp.async.cg.shared.global [%0], [%1], 16;" :: "r"(dst), "l"(src));
}
#define CP_COMMIT() asm volatile("cp.async.commit_group;" ::: "memory")
#define CP_WAIT0()  asm volatile("cp.async.wait_group 0;" ::: "memory")
#define CP_WAIT1()  asm volatile("cp.async.wait_group 1;" ::: "memory")

// slice geometry: 128 rows x 64 bf16 cols, row stride 144 bytes
#define SLW 144
#define SLT (128 * SLW)                 // 18432 per slice tile
#define OFF_AH 0
#define OFF_AL SLT
#define OFF_BH (2 * SLT)
#define OFF_BL (3 * SLT)
#define DYN_QK (4 * SLT)                // 73728; stash(67584)+red2(2048) alias
#define DYN_PV (4 * SLT)
#define STASHW 132

// ---------------------------------------------------------------------------
// prep: split fp32 rows of Q and K into hi/lo bf16 (row-major, linear)
// ---------------------------------------------------------------------------
__global__ __launch_bounds__(256) void prep_qk_kernel(const float* __restrict__ Q,
                                                      const float* __restrict__ K) {
    const float* src = blockIdx.y ? K : Q;
    __nv_bfloat16* dh = blockIdx.y ? g_Kh : g_Qh;
    __nv_bfloat16* dl = blockIdx.y ? g_Kl : g_Ql;
    size_t idx = (size_t)blockIdx.x * 256 + threadIdx.x;
    const float* p = src + idx * 8;
    float4 f0 = *(const float4*)p, f1 = *(const float4*)(p + 4);
    float l[8];
    uint4 hv, lv;
    hv.x = pack2_hi(f0.x, f0.y, l[0], l[1]);
    hv.y = pack2_hi(f0.z, f0.w, l[2], l[3]);
    hv.z = pack2_hi(f1.x, f1.y, l[4], l[5]);
    hv.w = pack2_hi(f1.z, f1.w, l[6], l[7]);
    lv.x = pack2(l[0], l[1]); lv.y = pack2(l[2], l[3]);
    lv.z = pack2(l[4], l[5]); lv.w = pack2(l[6], l[7]);
    *(uint4*)(dh + idx * 8) = hv;
    *(uint4*)(dl + idx * 8) = lv;
}

__global__ __launch_bounds__(256) void prep_vt_kernel(const float* __restrict__ V) {
    int chunk = blockIdx.x, b = blockIdx.y, tid = threadIdx.x;
#pragma unroll
    for (int g = 0; g < 8; g++) {
        int item = tid + g * 256;
        int r = item & 127;           // n (dv)
        int c8 = item >> 7;           // k-group
        int k0 = chunk * 128 + c8 * 8;
        float f[8], l[8];
#pragma unroll
        for (int j = 0; j < 8; j++)
            f[j] = V[((size_t)b * SKL + k0 + j) * DD + r];
        uint4 hv, lv;
        hv.x = pack2_hi(f[0], f[1], l[0], l[1]);
        hv.y = pack2_hi(f[2], f[3], l[2], l[3]);
        hv.z = pack2_hi(f[4], f[5], l[4], l[5]);
        hv.w = pack2_hi(f[6], f[7], l[6], l[7]);
        lv.x = pack2(l[0], l[1]); lv.y = pack2(l[2], l[3]);
        lv.z = pack2(l[4], l[5]); lv.w = pack2(l[6], l[7]);
        size_t dst = ((size_t)b * DD + r) * SKL + k0;
        *(uint4*)(g_Vth + dst) = hv;
        *(uint4*)(g_Vtl + dst) = lv;
    }
}

// ---------------------------------------------------------------------------
// qk: E = exp(scale * Q @ K^T) masked (masked -> 0), coalesced E write,
// per-(row,ktile) partial sums. grid (16 kt, 16 qt, 16 b), 256 thr, 2 CTA/SM.
// ---------------------------------------------------------------------------
__global__ __launch_bounds__(256, 2) void qk_mma_kernel(const int* __restrict__ mask,
                                                        float* __restrict__ S) {
    extern __shared__ char sm[];
    const uint32_t sb = (uint32_t)__cvta_generic_to_shared(sm);
    const int tid = threadIdx.x, wid = tid >> 5, lane = tid & 31;
    const int wm = wid >> 2, wn = wid & 3;
    const int kt = blockIdx.x, qt = blockIdx.y, b = blockIdx.z;
    const size_t rowbase = (size_t)b * SQL + qt * 128;

    // ldmatrix lane address offsets
    const int la_row = lane & 15;
    const int la_k   = (lane & 16) ? 16 : 0;
    const int lb_row = (lane & 7) + ((lane & 16) ? 8 : 0);
    const int lb_k   = (lane & 8) ? 16 : 0;

    float acc[4][4][4];
#pragma unroll
    for (int mt = 0; mt < 4; mt++)
#pragma unroll
        for (int nt = 0; nt < 4; nt++)
#pragma unroll
            for (int i = 0; i < 4; i++) acc[mt][nt][i] = 0.0f;

    const __nv_bfloat16* srcs[4] = {
        g_Qh + rowbase * DD, g_Ql + rowbase * DD,
        g_Kh + ((size_t)b * SKL + kt * 128) * DD,
        g_Kl + ((size_t)b * SKL + kt * 128) * DD};

#pragma unroll
    for (int sl = 0; sl < 2; sl++) {
        // stage 4 slice tiles via cp.async
#pragma unroll
        for (int t = 0; t < 4; t++) {
            uint32_t dstb = sb + t * SLT;
            const __nv_bfloat16* srcp = srcs[t] + sl * 64;
#pragma unroll
            for (int g = 0; g < 4; g++) {
                int idx = tid + g * 256;
                int row = idx >> 3, c16 = idx & 7;
                cpa16(dstb + row * SLW + c16 * 16, srcp + (size_t)row * DD + c16 * 8);
            }
        }
        CP_COMMIT();
        CP_WAIT0();
        __syncthreads();

#pragma unroll
        for (int ks = 0; ks < 4; ks++) {
            const int kb = ks * 32;
            uint32_t bh[4][2], bl[4][2];
#pragma unroll
            for (int ntp = 0; ntp < 2; ntp++) {
                uint32_t ba = sb + OFF_BH + (uint32_t)(wn * 32 + ntp * 16 + lb_row) * SLW + kb + lb_k;
                ldsm4(bh[2 * ntp][0], bh[2 * ntp][1], bh[2 * ntp + 1][0], bh[2 * ntp + 1][1], ba);
                ldsm4(bl[2 * ntp][0], bl[2 * ntp][1], bl[2 * ntp + 1][0], bl[2 * ntp + 1][1], ba + SLT);
            }
#pragma unroll
            for (int mt = 0; mt < 4; mt++) {
                uint32_t aa = sb + OFF_AH + (uint32_t)(wm * 64 + mt * 16 + la_row) * SLW + kb + la_k;
                uint32_t ah0, ah1, ah2, ah3, al0, al1, al2, al3;
                ldsm4(ah0, ah1, ah2, ah3, aa);
                ldsm4(al0, al1, al2, al3, aa + SLT);
#pragma unroll
                for (int nt = 0; nt < 4; nt++) {
                    mma_bf16(acc[mt][nt], ah0, ah1, ah2, ah3, bh[nt][0], bh[nt][1]);
                    mma_bf16(acc[mt][nt], al0, al1, al2, al3, bh[nt][0], bh[nt][1]);
                    mma_bf16(acc[mt][nt], ah0, ah1, ah2, ah3, bl[nt][0], bl[nt][1]);
                }
            }
        }
        __syncthreads();
    }

    // ---- epilogue: stage mask coalesced, exp in-place, coalesced E write ----
    int*   stashi = (int*)sm;                    // aliases tiles (MMA done)
    float* stashf = (float*)sm;
    float* red2   = (float*)(sm + 128 * STASHW * 4);   // 67584..69632

#pragma unroll
    for (int g = 0; g < 16; g++) {
        int idx = tid + g * 256;                 // 4096 int4 groups
        int r = idx >> 5, cg = idx & 31;
        *(int4*)&stashi[r * STASHW + cg * 4] =
            *(const int4*)(mask + (rowbase + r) * SKL + kt * 128 + cg * 4);
    }
    __syncthreads();

    const float scale = 0.08838834764831845f;
    const int rq = lane >> 2, qq = (lane & 3) * 2;
#pragma unroll
    for (int mt = 0; mt < 4; mt++) {
        const int rl1 = wm * 64 + mt * 16 + rq, rl2 = rl1 + 8;
        float s1 = 0.0f, s2 = 0.0f;
#pragma unroll
        for (int nt = 0; nt < 4; nt++) {
            int cl = wn * 32 + nt * 8 + qq;
            int2 m1 = *(const int2*)&stashi[rl1 * STASHW + cl];
            int2 m2 = *(const int2*)&stashi[rl2 * STASHW + cl];
            float* c = acc[mt][nt];
            float e0 = m1.x ? __expf(c[0] * scale) : 0.0f;
            float e1 = m1.y ? __expf(c[1] * scale) : 0.0f;
            float e2 = m2.x ? __expf(c[2] * scale) : 0.0f;
            float e3 = m2.y ? __expf(c[3] * scale) : 0.0f;
            stashf[rl1 * STASHW + cl]     = e0;
            stashf[rl1 * STASHW + cl + 1] = e1;
            stashf[rl2 * STASHW + cl]     = e2;
            stashf[rl2 * STASHW + cl + 1] = e3;
            s1 += e0 + e1;
            s2 += e2 + e3;
        }
#pragma unroll
        for (int off = 1; off <= 2; off <<= 1) {
            s1 += __shfl_xor_sync(0xffffffffu, s1, off);
            s2 += __shfl_xor_sync(0xffffffffu, s2, off);
        }
        if ((lane & 3) == 0) {
            red2[wn * 128 + rl1] = s1;
            red2[wn * 128 + rl2] = s2;
        }
    }
    __syncthreads();
    if (tid < 128) {
        float s = red2[tid] + red2[128 + tid] + red2[256 + tid] + red2[384 + tid];
        g_ps[(rowbase + tid) * NTILES + kt] = s;
    }

#pragma unroll
    for (int g = 0; g < 16; g++) {
        int idx = tid + g * 256;
        int r = idx >> 5, cg = idx & 31;
        *(float4*)(S + (rowbase + r) * SKL + kt * 128 + cg * 4) =
            *(const float4*)&stashf[r * STASHW + cg * 4];
    }
}

// ---------------------------------------------------------------------------
// pv: inv = 1/sum(partials); P = E * inv written in-place (final attn);
// ctx = P @ V with A fragments built in registers from global E loads and
// double-buffered V^T in smem. grid (16 qt, 16 b), 256 thr, 2 CTA/SM.
// ---------------------------------------------------------------------------
__global__ __launch_bounds__(256, 2) void pv_mma_kernel(float* __restrict__ S,
                                                        float* __restrict__ ctx) {
    extern __shared__ char sm[];
    const uint32_t sb = (uint32_t)__cvta_generic_to_shared(sm);
    const int tid = threadIdx.x, w = tid >> 5, lane = tid & 31;
    const int rq = lane >> 2, qq = (lane & 3) * 2;
    const int qt = blockIdx.x, b = blockIdx.y;
    const size_t rowbase = (size_t)b * SQL + qt * 128;
    const size_t grow1 = rowbase + w * 16 + rq;
    const size_t grow2 = grow1 + 8;

    const int lb_row = (lane & 7) + ((lane & 16) ? 8 : 0);
    const int lb_k   = (lane & 8) ? 16 : 0;

    // per-lane row inverses
    float inv1, inv2;
    {
        const float* p1 = g_ps + grow1 * NTILES;
        const float* p2 = g_ps + grow2 * NTILES;
        float s1 = 0.0f, s2 = 0.0f;
#pragma unroll
        for (int i = 0; i < 4; i++) {
            float4 v1 = *(const float4*)(p1 + i * 4);
            float4 v2 = *(const float4*)(p2 + i * 4);
            s1 += v1.x + v1.y + v1.z + v1.w;
            s2 += v2.x + v2.y + v2.z + v2.w;
        }
        inv1 = 1.0f / s1;
        inv2 = 1.0f / s2;
    }

    float acc[16][4];
#pragma unroll
    for (int nt = 0; nt < 16; nt++)
#pragma unroll
        for (int i = 0; i < 4; i++) acc[nt][i] = 0.0f;

    const __nv_bfloat16* vth = g_Vth + (size_t)b * DD * SKL;
    const __nv_bfloat16* vtl = g_Vtl + (size_t)b * DD * SKL;

    auto stage = [&](int s, int st) {
        uint32_t d0 = sb + (uint32_t)st * 2 * SLT;
#pragma unroll
        for (int g = 0; g < 4; g++) {
            int idx = tid + g * 256;
            int n = idx >> 3, c16 = idx & 7;
            size_t src = (size_t)n * SKL + s * 64 + c16 * 8;
            cpa16(d0 + n * SLW + c16 * 16, vth + src);
            cpa16(d0 + SLT + n * SLW + c16 * 16, vtl + src);
        }
        CP_COMMIT();
    };

    stage(0, 0);
    for (int s = 0; s < 32; s++) {
        if (s < 31) { stage(s + 1, (s + 1) & 1); CP_WAIT1(); }
        else        { CP_WAIT0(); }
        __syncthreads();

        const uint32_t bbase = sb + (uint32_t)(s & 1) * 2 * SLT;
        const int kbase = s * 64;
#pragma unroll
        for (int ks = 0; ks < 4; ks++) {
            const int col = kbase + ks * 16 + qq;
            float2 e00 = *(const float2*)(S + grow1 * SKL + col);
            float2 e01 = *(const float2*)(S + grow1 * SKL + col + 8);
            float2 e10 = *(const float2*)(S + grow2 * SKL + col);
            float2 e11 = *(const float2*)(S + grow2 * SKL + col + 8);
            float2 p00 = make_float2(e00.x * inv1, e00.y * inv1);
            float2 p01 = make_float2(e01.x * inv1, e01.y * inv1);
            float2 p10 = make_float2(e10.x * inv2, e10.y * inv2);
            float2 p11 = make_float2(e11.x * inv2, e11.y * inv2);
            *(float2*)(S + grow1 * SKL + col)     = p00;
            *(float2*)(S + grow1 * SKL + col + 8) = p01;
            *(float2*)(S + grow2 * SKL + col)     = p10;
            *(float2*)(S + grow2 * SKL + col + 8) = p11;

            float l0, l1;
            uint32_t ah0 = pack2_hi(p00.x, p00.y, l0, l1);
            uint32_t al0 = pack2(l0, l1);
            uint32_t ah1 = pack2_hi(p10.x, p10.y, l0, l1);
            uint32_t al1 = pack2(l0, l1);
            uint32_t ah2 = pack2_hi(p01.x, p01.y, l0, l1);
            uint32_t al2 = pack2(l0, l1);
            uint32_t ah3 = pack2_hi(p11.x, p11.y, l0, l1);
            uint32_t al3 = pack2(l0, l1);

#pragma unroll
            for (int ntp = 0; ntp < 8; ntp++) {
                uint32_t ba = bbase + (uint32_t)(ntp * 16 + lb_row) * SLW + ks * 32 + lb_k;
                uint32_t bh0, bh1, bh2, bh3, bl0, bl1, bl2, bl3;
                ldsm4(bh0, bh1, bh2, bh3, ba);
                ldsm4(bl0, bl1, bl2, bl3, ba + SLT);
                mma_bf16(acc[2 * ntp], ah0, ah1, ah2, ah3, bh0, bh1);
                mma_bf16(acc[2 * ntp], al0, al1, al2, al3, bh0, bh1);
                mma_bf16(acc[2 * ntp], ah0, ah1, ah2, ah3, bl0, bl1);
                mma_bf16(acc[2 * ntp + 1], ah0, ah1, ah2, ah3, bh2, bh3);
                mma_bf16(acc[2 * ntp + 1], al0, al1, al2, al3, bh2, bh3);
                mma_bf16(acc[2 * ntp + 1], ah0, ah1, ah2, ah3, bl2, bl3);
            }
        }
        __syncthreads();
    }

    // ctx written directly from fragments
#pragma unroll
    for (int nt = 0; nt < 16; nt++) {
        int cg = nt * 8 + qq;
        *(float2*)(ctx + grow1 * DD + cg) = make_float2(acc[nt][0], acc[nt][1]);
        *(float2*)(ctx + grow2 * DD + cg) = make_float2(acc[nt][2], acc[nt][3]);
    }
}

// ---------------------------------------------------------------------------
extern "C" void kernel_launch(void* const* d_in, const int* in_sizes, int n_in,
                              void* d_out, int out_size) {
    const float* Q    = (const float*)d_in[0];
    const float* K    = (const float*)d_in[1];
    const float* V    = (const float*)d_in[2];
    const int*   mask = (const int*)d_in[3];

    float* ctx  = (float*)d_out;
    float* attn = (float*)d_out + (size_t)BB * SQL * DD;

    static bool attr_done = false;
    if (!attr_done) {
        cudaFuncSetAttribute(qk_mma_kernel, cudaFuncAttributeMaxDynamicSharedMemorySize, DYN_QK);
        cudaFuncSetAttribute(pv_mma_kernel, cudaFuncAttributeMaxDynamicSharedMemorySize, DYN_PV);
        attr_done = true;
    }

    prep_qk_kernel<<<dim3(2048, 2), 256>>>(Q, K);
    prep_vt_kernel<<<dim3(16, BB), 256>>>(V);
    qk_mma_kernel<<<dim3(16, 16, BB), 256, DYN_QK>>>(mask, attn);
    pv_mma_kernel<<<dim3(16, BB), 256, DYN_PV>>>(attn, ctx);
}

// round 8
// speedup vs baseline: 1.0424x; 1.0424x over previous
#include <cuda_runtime.h>
#include <cuda_bf16.h>
#include <cstdint>
#include <math.h>

#define BB   16
#define SQL  2048
#define SKL  2048
#define DD   128
#define NROWS (BB * SQL)
#define NTILES 16

// ---------------- scratch (__device__ globals; no allocation) ----------------
__device__ __nv_bfloat16 g_Qh[(size_t)BB * SQL * DD];
__device__ __nv_bfloat16 g_Ql[(size_t)BB * SQL * DD];
__device__ __nv_bfloat16 g_Kh[(size_t)BB * SKL * DD];
__device__ __nv_bfloat16 g_Kl[(size_t)BB * SKL * DD];
__device__ __nv_bfloat16 g_Vth[(size_t)BB * DD * SKL];   // V^T: [b][dv][k]
__device__ __nv_bfloat16 g_Vtl[(size_t)BB * DD * SKL];
__device__ float g_ps[(size_t)NROWS * NTILES];           // per-(row,ktile) sum exp

// ---------------- helpers ----------------------------------------------------
__device__ __forceinline__ uint32_t pack2_hi(float a, float b, float& la, float& lb) {
    __nv_bfloat16 ha = __float2bfloat16_rn(a), hb = __float2bfloat16_rn(b);
    la = a - __bfloat162float(ha);
    lb = b - __bfloat162float(hb);
    return (uint32_t)__bfloat16_as_ushort(ha) | ((uint32_t)__bfloat16_as_ushort(hb) << 16);
}
__device__ __forceinline__ uint32_t pack2(float a, float b) {
    __nv_bfloat16 ha = __float2bfloat16_rn(a), hb = __float2bfloat16_rn(b);
    return (uint32_t)__bfloat16_as_ushort(ha) | ((uint32_t)__bfloat16_as_ushort(hb) << 16);
}
__device__ __forceinline__ void mma_bf16(float* c, uint32_t a0, uint32_t a1,
                                         uint32_t a2, uint32_t a3,
                                         uint32_t b0, uint32_t b1) {
    asm volatile(
        "mma.sync.aligned.m16n8k16.row.col.f32.bf16.bf16.f32 "
        "{%0,%1,%2,%3}, {%4,%5,%6,%7}, {%8,%9}, {%0,%1,%2,%3};"
        : "+f"(c[0]), "+f"(c[1]), "+f"(c[2]), "+f"(c[3])
        : "r"(a0), "r"(a1), "r"(a2), "r"(a3), "r"(b0), "r"(b1));
}
__device__ __forceinline__ void ldsm4(uint32_t& r0, uint32_t& r1, uint32_t& r2,
                                      uint32_t& r3, uint32_t addr) {
    asm volatile("ldmatrix.sync.aligned.m8n8.x4.shared.b16 {%0,%1,%2,%3}, [%4];"
                 : "=r"(r0), "=r"(r1), "=r"(r2), "=r"(r3) : "r"(addr));
}
__device__ __forceinline__ void cpa16(uint32_t dst, const void* src) {
    asm volatile("cp.async.cg.shared.global [%0], [%1], 16;" :: "r"(dst), "l"(src));
}
#define CP_COMMIT() asm volatile("cp.async.commit_group;" ::: "memory")
#define CP_WAIT0()  asm volatile("cp.async.wait_group 0;" ::: "memory")
#define CP_WAIT1()  asm volatile("cp.async.wait_group 1;" ::: "memory")

// qk slice geometry: 128 rows x 64 bf16 cols, row stride 144 bytes
#define SLW 144
#define SLT (128 * SLW)                 // 18432 per slice tile
#define OFF_AH 0
#define OFF_AL SLT
#define OFF_BH (2 * SLT)
#define OFF_BL (3 * SLT)
#define DYN_QK (4 * SLT)                // 73728
#define STASHW 132

// pv geometry: 32-k slices; E fp32 128x32 (stride 144B), V hi/lo 128x32 bf16 (stride 80B)
#define PV_ET 18432                     // E tile bytes (128*144)
#define PV_VT 10240                     // one V (hi or lo) tile (128*80)
#define PV_VB (2 * PV_VT)               // 20480 hi+lo
#define PV_VOFF (2 * PV_ET)             // 36864
#define PV_INV (PV_VOFF + 2 * PV_VB)    // 77824
#define DYN_PV (PV_INV + 512)           // 78336

// ---------------------------------------------------------------------------
// prep: split fp32 rows of Q and K into hi/lo bf16 (row-major, linear)
// ---------------------------------------------------------------------------
__global__ __launch_bounds__(256) void prep_qk_kernel(const float* __restrict__ Q,
                                                      const float* __restrict__ K) {
    const float* src = blockIdx.y ? K : Q;
    __nv_bfloat16* dh = blockIdx.y ? g_Kh : g_Qh;
    __nv_bfloat16* dl = blockIdx.y ? g_Kl : g_Ql;
    size_t idx = (size_t)blockIdx.x * 256 + threadIdx.x;
    const float* p = src + idx * 8;
    float4 f0 = *(const float4*)p, f1 = *(const float4*)(p + 4);
    float l[8];
    uint4 hv, lv;
    hv.x = pack2_hi(f0.x, f0.y, l[0], l[1]);
    hv.y = pack2_hi(f0.z, f0.w, l[2], l[3]);
    hv.z = pack2_hi(f1.x, f1.y, l[4], l[5]);
    hv.w = pack2_hi(f1.z, f1.w, l[6], l[7]);
    lv.x = pack2(l[0], l[1]); lv.y = pack2(l[2], l[3]);
    lv.z = pack2(l[4], l[5]); lv.w = pack2(l[6], l[7]);
    *(uint4*)(dh + idx * 8) = hv;
    *(uint4*)(dl + idx * 8) = lv;
}

__global__ __launch_bounds__(256) void prep_vt_kernel(const float* __restrict__ V) {
    int chunk = blockIdx.x, b = blockIdx.y, tid = threadIdx.x;
#pragma unroll
    for (int g = 0; g < 8; g++) {
        int item = tid + g * 256;
        int r = item & 127;           // n (dv)
        int c8 = item >> 7;           // k-group
        int k0 = chunk * 128 + c8 * 8;
        float f[8], l[8];
#pragma unroll
        for (int j = 0; j < 8; j++)
            f[j] = V[((size_t)b * SKL + k0 + j) * DD + r];
        uint4 hv, lv;
        hv.x = pack2_hi(f[0], f[1], l[0], l[1]);
        hv.y = pack2_hi(f[2], f[3], l[2], l[3]);
        hv.z = pack2_hi(f[4], f[5], l[4], l[5]);
        hv.w = pack2_hi(f[6], f[7], l[6], l[7]);
        lv.x = pack2(l[0], l[1]); lv.y = pack2(l[2], l[3]);
        lv.z = pack2(l[4], l[5]); lv.w = pack2(l[6], l[7]);
        size_t dst = ((size_t)b * DD + r) * SKL + k0;
        *(uint4*)(g_Vth + dst) = hv;
        *(uint4*)(g_Vtl + dst) = lv;
    }
}

// ---------------------------------------------------------------------------
// qk: E = exp(scale * Q @ K^T) masked (masked -> 0), coalesced E write,
// per-(row,ktile) partial sums. grid (16 kt, 16 qt, 16 b), 256 thr, 2 CTA/SM.
// ---------------------------------------------------------------------------
__global__ __launch_bounds__(256, 2) void qk_mma_kernel(const int* __restrict__ mask,
                                                        float* __restrict__ S) {
    extern __shared__ char sm[];
    const uint32_t sb = (uint32_t)__cvta_generic_to_shared(sm);
    const int tid = threadIdx.x, wid = tid >> 5, lane = tid & 31;
    const int wm = wid >> 2, wn = wid & 3;
    const int kt = blockIdx.x, qt = blockIdx.y, b = blockIdx.z;
    const size_t rowbase = (size_t)b * SQL + qt * 128;

    const int la_row = lane & 15;
    const int la_k   = (lane & 16) ? 16 : 0;
    const int lb_row = (lane & 7) + ((lane & 16) ? 8 : 0);
    const int lb_k   = (lane & 8) ? 16 : 0;

    float acc[4][4][4];
#pragma unroll
    for (int mt = 0; mt < 4; mt++)
#pragma unroll
        for (int nt = 0; nt < 4; nt++)
#pragma unroll
            for (int i = 0; i < 4; i++) acc[mt][nt][i] = 0.0f;

    const __nv_bfloat16* srcs[4] = {
        g_Qh + rowbase * DD, g_Ql + rowbase * DD,
        g_Kh + ((size_t)b * SKL + kt * 128) * DD,
        g_Kl + ((size_t)b * SKL + kt * 128) * DD};

#pragma unroll
    for (int sl = 0; sl < 2; sl++) {
#pragma unroll
        for (int t = 0; t < 4; t++) {
            uint32_t dstb = sb + t * SLT;
            const __nv_bfloat16* srcp = srcs[t] + sl * 64;
#pragma unroll
            for (int g = 0; g < 4; g++) {
                int idx = tid + g * 256;
                int row = idx >> 3, c16 = idx & 7;
                cpa16(dstb + row * SLW + c16 * 16, srcp + (size_t)row * DD + c16 * 8);
            }
        }
        CP_COMMIT();
        CP_WAIT0();
        __syncthreads();

#pragma unroll
        for (int ks = 0; ks < 4; ks++) {
            const int kb = ks * 32;
            uint32_t bh[4][2], bl[4][2];
#pragma unroll
            for (int ntp = 0; ntp < 2; ntp++) {
                uint32_t ba = sb + OFF_BH + (uint32_t)(wn * 32 + ntp * 16 + lb_row) * SLW + kb + lb_k;
                ldsm4(bh[2 * ntp][0], bh[2 * ntp][1], bh[2 * ntp + 1][0], bh[2 * ntp + 1][1], ba);
                ldsm4(bl[2 * ntp][0], bl[2 * ntp][1], bl[2 * ntp + 1][0], bl[2 * ntp + 1][1], ba + SLT);
            }
#pragma unroll
            for (int mt = 0; mt < 4; mt++) {
                uint32_t aa = sb + OFF_AH + (uint32_t)(wm * 64 + mt * 16 + la_row) * SLW + kb + la_k;
                uint32_t ah0, ah1, ah2, ah3, al0, al1, al2, al3;
                ldsm4(ah0, ah1, ah2, ah3, aa);
                ldsm4(al0, al1, al2, al3, aa + SLT);
#pragma unroll
                for (int nt = 0; nt < 4; nt++) {
                    mma_bf16(acc[mt][nt], ah0, ah1, ah2, ah3, bh[nt][0], bh[nt][1]);
                    mma_bf16(acc[mt][nt], al0, al1, al2, al3, bh[nt][0], bh[nt][1]);
                    mma_bf16(acc[mt][nt], ah0, ah1, ah2, ah3, bl[nt][0], bl[nt][1]);
                }
            }
        }
        __syncthreads();
    }

    // epilogue: stage mask coalesced, exp, partial sums, coalesced E write
    int*   stashi = (int*)sm;
    float* stashf = (float*)sm;
    float* red2   = (float*)(sm + 128 * STASHW * 4);

#pragma unroll
    for (int g = 0; g < 16; g++) {
        int idx = tid + g * 256;
        int r = idx >> 5, cg = idx & 31;
        *(int4*)&stashi[r * STASHW + cg * 4] =
            *(const int4*)(mask + (rowbase + r) * SKL + kt * 128 + cg * 4);
    }
    __syncthreads();

    const float scale = 0.08838834764831845f;
    const int rq = lane >> 2, qq = (lane & 3) * 2;
#pragma unroll
    for (int mt = 0; mt < 4; mt++) {
        const int rl1 = wm * 64 + mt * 16 + rq, rl2 = rl1 + 8;
        float s1 = 0.0f, s2 = 0.0f;
#pragma unroll
        for (int nt = 0; nt < 4; nt++) {
            int cl = wn * 32 + nt * 8 + qq;
            int2 m1 = *(const int2*)&stashi[rl1 * STASHW + cl];
            int2 m2 = *(const int2*)&stashi[rl2 * STASHW + cl];
            float* c = acc[mt][nt];
            float e0 = m1.x ? __expf(c[0] * scale) : 0.0f;
            float e1 = m1.y ? __expf(c[1] * scale) : 0.0f;
            float e2 = m2.x ? __expf(c[2] * scale) : 0.0f;
            float e3 = m2.y ? __expf(c[3] * scale) : 0.0f;
            stashf[rl1 * STASHW + cl]     = e0;
            stashf[rl1 * STASHW + cl + 1] = e1;
            stashf[rl2 * STASHW + cl]     = e2;
            stashf[rl2 * STASHW + cl + 1] = e3;
            s1 += e0 + e1;
            s2 += e2 + e3;
        }
#pragma unroll
        for (int off = 1; off <= 2; off <<= 1) {
            s1 += __shfl_xor_sync(0xffffffffu, s1, off);
            s2 += __shfl_xor_sync(0xffffffffu, s2, off);
        }
        if ((lane & 3) == 0) {
            red2[wn * 128 + rl1] = s1;
            red2[wn * 128 + rl2] = s2;
        }
    }
    __syncthreads();
    if (tid < 128) {
        float s = red2[tid] + red2[128 + tid] + red2[256 + tid] + red2[384 + tid];
        g_ps[(rowbase + tid) * NTILES + kt] = s;
    }

#pragma unroll
    for (int g = 0; g < 16; g++) {
        int idx = tid + g * 256;
        int r = idx >> 5, cg = idx & 31;
        *(float4*)(S + (rowbase + r) * SKL + kt * 128 + cg * 4) =
            *(const float4*)&stashf[r * STASHW + cg * 4];
    }
}

// ---------------------------------------------------------------------------
// pv: ctx = (E @ V) * inv; P = E * inv written coalesced from smem (final
// attn). E and V^T staged via cp.async, double-buffered 32-k slices.
// grid (16 qt, 16 b), 256 thr, 2 CTA/SM.
// ---------------------------------------------------------------------------
__global__ __launch_bounds__(256, 2) void pv_mma_kernel(float* __restrict__ S,
                                                        float* __restrict__ ctx) {
    extern __shared__ char sm[];
    const uint32_t sb = (uint32_t)__cvta_generic_to_shared(sm);
    const int tid = threadIdx.x, w = tid >> 5, lane = tid & 31;
    const int rq = lane >> 2, qq = (lane & 3) * 2;
    const int qt = blockIdx.x, b = blockIdx.y;
    const size_t rowbase = (size_t)b * SQL + qt * 128;
    const size_t grow1 = rowbase + w * 16 + rq;
    const size_t grow2 = grow1 + 8;

    const int lb_row = (lane & 7) + ((lane & 16) ? 8 : 0);
    const int lb_k   = (lane & 8) ? 16 : 0;

    float* sInv = (float*)(sm + PV_INV);
    if (tid < 128) {
        const float* p = g_ps + (rowbase + tid) * NTILES;
        float s = 0.0f;
#pragma unroll
        for (int i = 0; i < 4; i++) {
            float4 v = *(const float4*)(p + i * 4);
            s += v.x + v.y + v.z + v.w;
        }
        sInv[tid] = 1.0f / s;
    }

    float acc[16][4];
#pragma unroll
    for (int nt = 0; nt < 16; nt++)
#pragma unroll
        for (int i = 0; i < 4; i++) acc[nt][i] = 0.0f;

    const __nv_bfloat16* vth = g_Vth + (size_t)b * DD * SKL;
    const __nv_bfloat16* vtl = g_Vtl + (size_t)b * DD * SKL;

    auto stage = [&](int s, int st) {
        uint32_t eb = sb + st * PV_ET;
#pragma unroll
        for (int g = 0; g < 4; g++) {
            int idx = tid + g * 256;            // 1024 chunks: 128 rows x 8
            int row = idx >> 3, c = idx & 7;
            cpa16(eb + row * 144 + c * 16,
                  S + (rowbase + row) * SKL + s * 32 + c * 4);
        }
        uint32_t vb = sb + PV_VOFF + st * PV_VB;
#pragma unroll
        for (int g = 0; g < 2; g++) {
            int idx = tid + g * 256;            // 512 chunks: 128 rows x 4
            int row = idx >> 2, c = idx & 3;
            size_t src = (size_t)row * SKL + s * 32 + c * 8;
            cpa16(vb + row * 80 + c * 16, vth + src);
            cpa16(vb + PV_VT + row * 80 + c * 16, vtl + src);
        }
        CP_COMMIT();
    };

    stage(0, 0);
    float inv1 = 0.0f, inv2 = 0.0f;
    for (int s = 0; s < 64; s++) {
        if (s < 63) { stage(s + 1, (s + 1) & 1); CP_WAIT1(); }
        else        { CP_WAIT0(); }
        __syncthreads();
        if (s == 0) { inv1 = sInv[w * 16 + rq]; inv2 = sInv[w * 16 + rq + 8]; }

        const char* ebp = sm + (s & 1) * PV_ET;
        const uint32_t vb = sb + PV_VOFF + (uint32_t)(s & 1) * PV_VB;
        const int r1o = (w * 16 + rq) * 144, r2o = r1o + 8 * 144;

#pragma unroll
        for (int ks = 0; ks < 2; ks++) {
            const int co = ks * 64 + qq * 4;    // byte offset of col ks*16+qq
            float2 e00 = *(const float2*)(ebp + r1o + co);
            float2 e01 = *(const float2*)(ebp + r1o + co + 32);
            float2 e10 = *(const float2*)(ebp + r2o + co);
            float2 e11 = *(const float2*)(ebp + r2o + co + 32);

            float l0, l1;
            uint32_t ah0 = pack2_hi(e00.x, e00.y, l0, l1);
            uint32_t al0 = pack2(l0, l1);
            uint32_t ah1 = pack2_hi(e10.x, e10.y, l0, l1);
            uint32_t al1 = pack2(l0, l1);
            uint32_t ah2 = pack2_hi(e01.x, e01.y, l0, l1);
            uint32_t al2 = pack2(l0, l1);
            uint32_t ah3 = pack2_hi(e11.x, e11.y, l0, l1);
            uint32_t al3 = pack2(l0, l1);

#pragma unroll
            for (int ntp = 0; ntp < 8; ntp++) {
                uint32_t ba = vb + (uint32_t)(ntp * 16 + lb_row) * 80 + ks * 32 + lb_k;
                uint32_t bh0, bh1, bh2, bh3, bl0, bl1, bl2, bl3;
                ldsm4(bh0, bh1, bh2, bh3, ba);
                ldsm4(bl0, bl1, bl2, bl3, ba + PV_VT);
                mma_bf16(acc[2 * ntp], ah0, ah1, ah2, ah3, bh0, bh1);
                mma_bf16(acc[2 * ntp], al0, al1, al2, al3, bh0, bh1);
                mma_bf16(acc[2 * ntp], ah0, ah1, ah2, ah3, bl0, bl1);
                mma_bf16(acc[2 * ntp + 1], ah0, ah1, ah2, ah3, bh2, bh3);
                mma_bf16(acc[2 * ntp + 1], al0, al1, al2, al3, bh2, bh3);
                mma_bf16(acc[2 * ntp + 1], ah0, ah1, ah2, ah3, bl2, bl3);
            }
        }

        // coalesced P write from smem: P = E * inv_row
#pragma unroll
        for (int g = 0; g < 4; g++) {
            int idx = tid + g * 256;
            int row = idx >> 3, c4 = idx & 7;
            float4 e = *(const float4*)(ebp + row * 144 + c4 * 16);
            float iv = sInv[row];
            e.x *= iv; e.y *= iv; e.z *= iv; e.w *= iv;
            *(float4*)(S + (rowbase + row) * SKL + s * 32 + c4 * 4) = e;
        }
        __syncthreads();
    }

    // ctx = acc * inv
#pragma unroll
    for (int nt = 0; nt < 16; nt++) {
        int cg = nt * 8 + qq;
        *(float2*)(ctx + grow1 * DD + cg) =
            make_float2(acc[nt][0] * inv1, acc[nt][1] * inv1);
        *(float2*)(ctx + grow2 * DD + cg) =
            make_float2(acc[nt][2] * inv2, acc[nt][3] * inv2);
    }
}

// ---------------------------------------------------------------------------
extern "C" void kernel_launch(void* const* d_in, const int* in_sizes, int n_in,
                              void* d_out, int out_size) {
    const float* Q    = (const float*)d_in[0];
    const float* K    = (const float*)d_in[1];
    const float* V    = (const float*)d_in[2];
    const int*   mask = (const int*)d_in[3];

    float* ctx  = (float*)d_out;
    float* attn = (float*)d_out + (size_t)BB * SQL * DD;

    static bool attr_done = false;
    if (!attr_done) {
        cudaFuncSetAttribute(qk_mma_kernel, cudaFuncAttributeMaxDynamicSharedMemorySize, DYN_QK);
        cudaFuncSetAttribute(pv_mma_kernel, cudaFuncAttributeMaxDynamicSharedMemorySize, DYN_PV);
        attr_done = true;
    }

    prep_qk_kernel<<<dim3(2048, 2), 256>>>(Q, K);
    prep_vt_kernel<<<dim3(16, BB), 256>>>(V);
    qk_mma_kernel<<<dim3(16, 16, BB), 256, DYN_QK>>>(mask, attn);
    pv_mma_kernel<<<dim3(16, BB), 256, DYN_PV>>>(attn, ctx);
}

// round 10
// speedup vs baseline: 1.2726x; 1.2208x over previous
#include <cuda_runtime.h>
#include <cuda_bf16.h>
#include <cstdint>
#include <math.h>

#define BB   16
#define SQL  2048
#define SKL  2048
#define DD   128
#define NROWS (BB * SQL)
#define NTILES 16

// ---------------- scratch (__device__ globals; no allocation) ----------------
__device__ __nv_bfloat16 g_Qh[(size_t)BB * SQL * DD];
__device__ __nv_bfloat16 g_Ql[(size_t)BB * SQL * DD];
__device__ __nv_bfloat16 g_Kh[(size_t)BB * SKL * DD];
__device__ __nv_bfloat16 g_Kl[(size_t)BB * SKL * DD];
__device__ __nv_bfloat16 g_Vth[(size_t)BB * DD * SKL];   // V^T: [b][dv][k]
__device__ __nv_bfloat16 g_Vtl[(size_t)BB * DD * SKL];
__device__ __nv_bfloat16 g_Eh[(size_t)NROWS * SKL];      // exp hi (bf16)
__device__ __nv_bfloat16 g_El[(size_t)NROWS * SKL];      // exp lo (bf16)
__device__ float g_ps[(size_t)NROWS * NTILES];           // per-(row,ktile) sum exp

// ---------------- helpers ----------------------------------------------------
__device__ __forceinline__ uint32_t pack2_hi(float a, float b, float& la, float& lb) {
    __nv_bfloat16 ha = __float2bfloat16_rn(a), hb = __float2bfloat16_rn(b);
    la = a - __bfloat162float(ha);
    lb = b - __bfloat162float(hb);
    return (uint32_t)__bfloat16_as_ushort(ha) | ((uint32_t)__bfloat16_as_ushort(hb) << 16);
}
__device__ __forceinline__ uint32_t pack2(float a, float b) {
    __nv_bfloat16 ha = __float2bfloat16_rn(a), hb = __float2bfloat16_rn(b);
    return (uint32_t)__bfloat16_as_ushort(ha) | ((uint32_t)__bfloat16_as_ushort(hb) << 16);
}
__device__ __forceinline__ float2 unpack2(uint32_t u) {
    __nv_bfloat162 v = *reinterpret_cast<__nv_bfloat162*>(&u);
    return make_float2(__bfloat162float(v.x), __bfloat162float(v.y));
}
__device__ __forceinline__ void mma_bf16(float* c, uint32_t a0, uint32_t a1,
                                         uint32_t a2, uint32_t a3,
                                         uint32_t b0, uint32_t b1) {
    asm volatile(
        "mma.sync.aligned.m16n8k16.row.col.f32.bf16.bf16.f32 "
        "{%0,%1,%2,%3}, {%4,%5,%6,%7}, {%8,%9}, {%0,%1,%2,%3};"
        : "+f"(c[0]), "+f"(c[1]), "+f"(c[2]), "+f"(c[3])
        : "r"(a0), "r"(a1), "r"(a2), "r"(a3), "r"(b0), "r"(b1));
}
__device__ __forceinline__ void ldsm4(uint32_t& r0, uint32_t& r1, uint32_t& r2,
                                      uint32_t& r3, uint32_t addr) {
    asm volatile("ldmatrix.sync.aligned.m8n8.x4.shared.b16 {%0,%1,%2,%3}, [%4];"
                 : "=r"(r0), "=r"(r1), "=r"(r2), "=r"(r3) : "r"(addr));
}
__device__ __forceinline__ void cpa16(uint32_t dst, const void* src) {
    asm volatile("cp.async.cg.shared.global [%0], [%1], 16;" :: "r"(dst), "l"(src));
}
#define CP_COMMIT() asm volatile("cp.async.commit_group;" ::: "memory")
#define CP_WAIT0()  asm volatile("cp.async.wait_group 0;" ::: "memory")
#define CP_WAIT1()  asm volatile("cp.async.wait_group 1;" ::: "memory")

// tile geometry: 128 rows x 32 bf16 cols, row stride 80 bytes (conflict-free ldsm)
#define TW 80
#define TT (128 * TW)                   // 10240 per tile
#define BUFB (4 * TT)                   // 40960 per 4-tile buffer
#define STASHW 132
#define DYN_QK (2 * BUFB)               // 81920 (stash 67584 + red2 aliases)
#define DYN_PV (2 * BUFB + 512)         // 82432

// ---------------------------------------------------------------------------
// prep: split fp32 rows of Q and K into hi/lo bf16 (row-major, linear)
// ---------------------------------------------------------------------------
__global__ __launch_bounds__(256) void prep_qk_kernel(const float* __restrict__ Q,
                                                      const float* __restrict__ K) {
    const float* src = blockIdx.y ? K : Q;
    __nv_bfloat16* dh = blockIdx.y ? g_Kh : g_Qh;
    __nv_bfloat16* dl = blockIdx.y ? g_Kl : g_Ql;
    size_t idx = (size_t)blockIdx.x * 256 + threadIdx.x;
    const float* p = src + idx * 8;
    float4 f0 = *(const float4*)p, f1 = *(const float4*)(p + 4);
    float l[8];
    uint4 hv, lv;
    hv.x = pack2_hi(f0.x, f0.y, l[0], l[1]);
    hv.y = pack2_hi(f0.z, f0.w, l[2], l[3]);
    hv.z = pack2_hi(f1.x, f1.y, l[4], l[5]);
    hv.w = pack2_hi(f1.z, f1.w, l[6], l[7]);
    lv.x = pack2(l[0], l[1]); lv.y = pack2(l[2], l[3]);
    lv.z = pack2(l[4], l[5]); lv.w = pack2(l[6], l[7]);
    *(uint4*)(dh + idx * 8) = hv;
    *(uint4*)(dl + idx * 8) = lv;
}

__global__ __launch_bounds__(256) void prep_vt_kernel(const float* __restrict__ V) {
    int chunk = blockIdx.x, b = blockIdx.y, tid = threadIdx.x;
#pragma unroll
    for (int g = 0; g < 8; g++) {
        int item = tid + g * 256;
        int r = item & 127;           // n (dv)
        int c8 = item >> 7;           // k-group
        int k0 = chunk * 128 + c8 * 8;
        float f[8], l[8];
#pragma unroll
        for (int j = 0; j < 8; j++)
            f[j] = V[((size_t)b * SKL + k0 + j) * DD + r];
        uint4 hv, lv;
        hv.x = pack2_hi(f[0], f[1], l[0], l[1]);
        hv.y = pack2_hi(f[2], f[3], l[2], l[3]);
        hv.z = pack2_hi(f[4], f[5], l[4], l[5]);
        hv.w = pack2_hi(f[6], f[7], l[6], l[7]);
        lv.x = pack2(l[0], l[1]); lv.y = pack2(l[2], l[3]);
        lv.z = pack2(l[4], l[5]); lv.w = pack2(l[6], l[7]);
        size_t dst = ((size_t)b * DD + r) * SKL + k0;
        *(uint4*)(g_Vth + dst) = hv;
        *(uint4*)(g_Vtl + dst) = lv;
    }
}

// ---------------------------------------------------------------------------
// qk: E = exp(scale * Q @ K^T) masked (->0); writes split-bf16 Ehi/Elo +
// per-(row,ktile) partial sums. Pipelined 32-col slices.
// grid (16 kt, 16 qt, 16 b), 256 thr, 2 CTA/SM.
// ---------------------------------------------------------------------------
__global__ __launch_bounds__(256, 2) void qk_mma_kernel(const int* __restrict__ mask,
                                                        float* __restrict__ dummy) {
    extern __shared__ char sm[];
    const uint32_t sb = (uint32_t)__cvta_generic_to_shared(sm);
    const int tid = threadIdx.x, wid = tid >> 5, lane = tid & 31;
    const int wm = wid >> 2, wn = wid & 3;
    const int kt = blockIdx.x, qt = blockIdx.y, b = blockIdx.z;
    const size_t rowbase = (size_t)b * SQL + qt * 128;

    const int la_row = lane & 15;
    const int la_k   = (lane & 16) ? 16 : 0;
    const int lb_row = (lane & 7) + ((lane & 16) ? 8 : 0);
    const int lb_k   = (lane & 8) ? 16 : 0;

    float acc[4][4][4];
#pragma unroll
    for (int mt = 0; mt < 4; mt++)
#pragma unroll
        for (int nt = 0; nt < 4; nt++)
#pragma unroll
            for (int i = 0; i < 4; i++) acc[mt][nt][i] = 0.0f;

    const __nv_bfloat16* srcs[4] = {
        g_Qh + rowbase * DD, g_Ql + rowbase * DD,
        g_Kh + ((size_t)b * SKL + kt * 128) * DD,
        g_Kl + ((size_t)b * SKL + kt * 128) * DD};

    auto qstage = [&](int sl, int st) {
        uint32_t base = sb + (uint32_t)st * BUFB;
#pragma unroll
        for (int t = 0; t < 4; t++) {
            const __nv_bfloat16* sp = srcs[t] + sl * 32;
            uint32_t db = base + t * TT;
#pragma unroll
            for (int g = 0; g < 2; g++) {
                int idx = tid + g * 256;
                int row = idx >> 2, c = idx & 3;
                cpa16(db + row * TW + c * 16, sp + (size_t)row * DD + c * 8);
            }
        }
        CP_COMMIT();
    };

    qstage(0, 0);
#pragma unroll
    for (int sl = 0; sl < 4; sl++) {
        if (sl < 3) { qstage(sl + 1, (sl + 1) & 1); CP_WAIT1(); }
        else        { CP_WAIT0(); }
        __syncthreads();
        const uint32_t base = sb + (uint32_t)(sl & 1) * BUFB;
#pragma unroll
        for (int ks = 0; ks < 2; ks++) {
            const int kb = ks * 32;
            uint32_t bh[4][2], bl[4][2];
#pragma unroll
            for (int ntp = 0; ntp < 2; ntp++) {
                uint32_t ba = base + 2 * TT + (uint32_t)(wn * 32 + ntp * 16 + lb_row) * TW + kb + lb_k;
                ldsm4(bh[2 * ntp][0], bh[2 * ntp][1], bh[2 * ntp + 1][0], bh[2 * ntp + 1][1], ba);
                ldsm4(bl[2 * ntp][0], bl[2 * ntp][1], bl[2 * ntp + 1][0], bl[2 * ntp + 1][1], ba + TT);
            }
#pragma unroll
            for (int mt = 0; mt < 4; mt++) {
                uint32_t aa = base + (uint32_t)(wm * 64 + mt * 16 + la_row) * TW + kb + la_k;
                uint32_t ah0, ah1, ah2, ah3, al0, al1, al2, al3;
                ldsm4(ah0, ah1, ah2, ah3, aa);
                ldsm4(al0, al1, al2, al3, aa + TT);
#pragma unroll
                for (int nt = 0; nt < 4; nt++) {
                    mma_bf16(acc[mt][nt], ah0, ah1, ah2, ah3, bh[nt][0], bh[nt][1]);
                    mma_bf16(acc[mt][nt], al0, al1, al2, al3, bh[nt][0], bh[nt][1]);
                    mma_bf16(acc[mt][nt], ah0, ah1, ah2, ah3, bl[nt][0], bl[nt][1]);
                }
            }
        }
        __syncthreads();
    }

    // epilogue: mask (direct), exp, partial sums, stash, split-bf16 write
    float* stashf = (float*)sm;
    float* red2   = (float*)(sm + 128 * STASHW * 4);   // 67584

    const float scale = 0.08838834764831845f;
    const int rq = lane >> 2, qq = (lane & 3) * 2;
#pragma unroll
    for (int mt = 0; mt < 4; mt++) {
        const int rl1 = wm * 64 + mt * 16 + rq, rl2 = rl1 + 8;
        const size_t r1 = rowbase + rl1;
        float s1 = 0.0f, s2 = 0.0f;
#pragma unroll
        for (int nt = 0; nt < 4; nt++) {
            int cl = wn * 32 + nt * 8 + qq;
            int colg = kt * 128 + cl;
            int2 m1 = *(const int2*)(mask + r1 * SKL + colg);
            int2 m2 = *(const int2*)(mask + (r1 + 8) * SKL + colg);
            float* c = acc[mt][nt];
            float e0 = m1.x ? __expf(c[0] * scale) : 0.0f;
            float e1 = m1.y ? __expf(c[1] * scale) : 0.0f;
            float e2 = m2.x ? __expf(c[2] * scale) : 0.0f;
            float e3 = m2.y ? __expf(c[3] * scale) : 0.0f;
            stashf[rl1 * STASHW + cl]     = e0;
            stashf[rl1 * STASHW + cl + 1] = e1;
            stashf[rl2 * STASHW + cl]     = e2;
            stashf[rl2 * STASHW + cl + 1] = e3;
            s1 += e0 + e1;
            s2 += e2 + e3;
        }
#pragma unroll
        for (int off = 1; off <= 2; off <<= 1) {
            s1 += __shfl_xor_sync(0xffffffffu, s1, off);
            s2 += __shfl_xor_sync(0xffffffffu, s2, off);
        }
        if ((lane & 3) == 0) {
            red2[wn * 128 + rl1] = s1;
            red2[wn * 128 + rl2] = s2;
        }
    }
    __syncthreads();
    if (tid < 128) {
        float s = red2[tid] + red2[128 + tid] + red2[256 + tid] + red2[384 + tid];
        g_ps[(rowbase + tid) * NTILES + kt] = s;
    }

    // coalesced split write: Ehi/Elo bf16
#pragma unroll
    for (int g = 0; g < 16; g++) {
        int idx = tid + g * 256;
        int r = idx >> 5, cg = idx & 31;
        float4 e = *(const float4*)&stashf[r * STASHW + cg * 4];
        float l0, l1, l2, l3;
        uint32_t h0 = pack2_hi(e.x, e.y, l0, l1);
        uint32_t h1 = pack2_hi(e.z, e.w, l2, l3);
        size_t off = (rowbase + r) * SKL + kt * 128 + cg * 4;
        *(uint2*)(g_Eh + off) = make_uint2(h0, h1);
        *(uint2*)(g_El + off) = make_uint2(pack2(l0, l1), pack2(l2, l3));
    }
}

// ---------------------------------------------------------------------------
// pv: ctx = (E @ V) * inv; P = (Ehi+Elo) * inv written coalesced (final attn).
// Ehi/Elo/V^T staged via cp.async, double-buffered 32-k slices; A via ldsm.
// grid (16 qt, 16 b), 256 thr, 2 CTA/SM.
// ---------------------------------------------------------------------------
__global__ __launch_bounds__(256, 2) void pv_mma_kernel(float* __restrict__ attn,
                                                        float* __restrict__ ctx) {
    extern __shared__ char sm[];
    const uint32_t sb = (uint32_t)__cvta_generic_to_shared(sm);
    const int tid = threadIdx.x, w = tid >> 5, lane = tid & 31;
    const int rq = lane >> 2, qq = (lane & 3) * 2;
    const int qt = blockIdx.x, b = blockIdx.y;
    const size_t rowbase = (size_t)b * SQL + qt * 128;
    const size_t grow1 = rowbase + w * 16 + rq;
    const size_t grow2 = grow1 + 8;

    const int la_row = lane & 15;
    const int la_k   = (lane & 16) ? 16 : 0;
    const int lb_row = (lane & 7) + ((lane & 16) ? 8 : 0);
    const int lb_k   = (lane & 8) ? 16 : 0;

    float* sInv = (float*)(sm + 2 * BUFB);
    if (tid < 128) {
        const float* p = g_ps + (rowbase + tid) * NTILES;
        float s = 0.0f;
#pragma unroll
        for (int i = 0; i < 4; i++) {
            float4 v = *(const float4*)(p + i * 4);
            s += v.x + v.y + v.z + v.w;
        }
        sInv[tid] = 1.0f / s;
    }

    float acc[16][4];
#pragma unroll
    for (int nt = 0; nt < 16; nt++)
#pragma unroll
        for (int i = 0; i < 4; i++) acc[nt][i] = 0.0f;

    const __nv_bfloat16* vth = g_Vth + (size_t)b * DD * SKL;
    const __nv_bfloat16* vtl = g_Vtl + (size_t)b * DD * SKL;
    const __nv_bfloat16* eh = g_Eh + rowbase * SKL;
    const __nv_bfloat16* el = g_El + rowbase * SKL;

    // buffer layout per st: Eh(TT) El(TT) Vh(TT) Vl(TT)
    auto stage = [&](int s, int st) {
        uint32_t base = sb + (uint32_t)st * BUFB;
#pragma unroll
        for (int g = 0; g < 2; g++) {
            int idx = tid + g * 256;
            int row = idx >> 2, c = idx & 3;
            size_t eoff = (size_t)row * SKL + s * 32 + c * 8;
            cpa16(base + row * TW + c * 16, eh + eoff);
            cpa16(base + TT + row * TW + c * 16, el + eoff);
            size_t voff = (size_t)row * SKL + s * 32 + c * 8;
            cpa16(base + 2 * TT + row * TW + c * 16, vth + voff);
            cpa16(base + 3 * TT + row * TW + c * 16, vtl + voff);
        }
        CP_COMMIT();
    };

    stage(0, 0);
    float inv1 = 0.0f, inv2 = 0.0f;
    for (int s = 0; s < 64; s++) {
        if (s < 63) { stage(s + 1, (s + 1) & 1); CP_WAIT1(); }
        else        { CP_WAIT0(); }
        __syncthreads();
        if (s == 0) { inv1 = sInv[w * 16 + rq]; inv2 = sInv[w * 16 + rq + 8]; }

        const uint32_t base = sb + (uint32_t)(s & 1) * BUFB;
#pragma unroll
        for (int ks = 0; ks < 2; ks++) {
            const int kb = ks * 32;
            uint32_t aa = base + (uint32_t)(w * 16 + la_row) * TW + kb + la_k;
            uint32_t ah0, ah1, ah2, ah3, al0, al1, al2, al3;
            ldsm4(ah0, ah1, ah2, ah3, aa);
            ldsm4(al0, al1, al2, al3, aa + TT);
#pragma unroll
            for (int ntp = 0; ntp < 8; ntp++) {
                uint32_t ba = base + 2 * TT + (uint32_t)(ntp * 16 + lb_row) * TW + kb + lb_k;
                uint32_t bh0, bh1, bh2, bh3, bl0, bl1, bl2, bl3;
                ldsm4(bh0, bh1, bh2, bh3, ba);
                ldsm4(bl0, bl1, bl2, bl3, ba + TT);
                mma_bf16(acc[2 * ntp], ah0, ah1, ah2, ah3, bh0, bh1);
                mma_bf16(acc[2 * ntp], al0, al1, al2, al3, bh0, bh1);
                mma_bf16(acc[2 * ntp], ah0, ah1, ah2, ah3, bl0, bl1);
                mma_bf16(acc[2 * ntp + 1], ah0, ah1, ah2, ah3, bh2, bh3);
                mma_bf16(acc[2 * ntp + 1], al0, al1, al2, al3, bh2, bh3);
                mma_bf16(acc[2 * ntp + 1], ah0, ah1, ah2, ah3, bl2, bl3);
            }
        }

        // coalesced P write: P = (hi + lo) * inv_row
        const char* ebp = sm + (s & 1) * BUFB;
#pragma unroll
        for (int g = 0; g < 4; g++) {
            int idx = tid + g * 256;
            int row = idx >> 3, c4 = idx & 7;      // 4 cols per thread
            uint2 h = *(const uint2*)(ebp + row * TW + c4 * 8);
            uint2 l = *(const uint2*)(ebp + TT + row * TW + c4 * 8);
            float2 h0 = unpack2(h.x), h1 = unpack2(h.y);
            float2 l0 = unpack2(l.x), l1 = unpack2(l.y);
            float iv = sInv[row];
            float4 pv;
            pv.x = (h0.x + l0.x) * iv;
            pv.y = (h0.y + l0.y) * iv;
            pv.z = (h1.x + l1.x) * iv;
            pv.w = (h1.y + l1.y) * iv;
            *(float4*)(attn + (rowbase + row) * SKL + s * 32 + c4 * 4) = pv;
        }
        __syncthreads();
    }

    // ctx = acc * inv
#pragma unroll
    for (int nt = 0; nt < 16; nt++) {
        int cg = nt * 8 + qq;
        *(float2*)(ctx + grow1 * DD + cg) =
            make_float2(acc[nt][0] * inv1, acc[nt][1] * inv1);
        *(float2*)(ctx + grow2 * DD + cg) =
            make_float2(acc[nt][2] * inv2, acc[nt][3] * inv2);
    }
}

// ---------------------------------------------------------------------------
extern "C" void kernel_launch(void* const* d_in, const int* in_sizes, int n_in,
                              void* d_out, int out_size) {
    const float* Q    = (const float*)d_in[0];
    const float* K    = (const float*)d_in[1];
    const float* V    = (const float*)d_in[2];
    const int*   mask = (const int*)d_in[3];

    float* ctx  = (float*)d_out;
    float* attn = (float*)d_out + (size_t)BB * SQL * DD;

    static bool attr_done = false;
    if (!attr_done) {
        cudaFuncSetAttribute(qk_mma_kernel, cudaFuncAttributeMaxDynamicSharedMemorySize, DYN_QK);
        cudaFuncSetAttribute(pv_mma_kernel, cudaFuncAttributeMaxDynamicSharedMemorySize, DYN_PV);
        attr_done = true;
    }

    prep_qk_kernel<<<dim3(2048, 2), 256>>>(Q, K);
    prep_vt_kernel<<<dim3(16, BB), 256>>>(V);
    qk_mma_kernel<<<dim3(16, 16, BB), 256, DYN_QK>>>(mask, attn);
    pv_mma_kernel<<<dim3(16, BB), 256, DYN_PV>>>(attn, ctx);
}

// round 11
// speedup vs baseline: 1.2847x; 1.0095x over previous
#include <cuda_runtime.h>
#include <cuda_bf16.h>
#include <cstdint>
#include <math.h>

#define BB   16
#define SQL  2048
#define SKL  2048
#define DD   128
#define NROWS (BB * SQL)
#define NTILES 16

// ---------------- scratch (__device__ globals; no allocation) ----------------
__device__ __nv_bfloat16 g_Qh[(size_t)BB * SQL * DD];
__device__ __nv_bfloat16 g_Ql[(size_t)BB * SQL * DD];
__device__ __nv_bfloat16 g_Kh[(size_t)BB * SKL * DD];
__device__ __nv_bfloat16 g_Kl[(size_t)BB * SKL * DD];
__device__ __nv_bfloat16 g_Vth[(size_t)BB * DD * SKL];   // V^T: [b][dv][k]
__device__ __nv_bfloat16 g_Vtl[(size_t)BB * DD * SKL];
__device__ __nv_bfloat16 g_Eh[(size_t)NROWS * SKL];      // exp hi (bf16)
__device__ __nv_bfloat16 g_El[(size_t)NROWS * SKL];      // exp lo (bf16)
__device__ float g_ps[(size_t)NROWS * NTILES];           // per-(row,ktile) sum exp

// ---------------- helpers ----------------------------------------------------
__device__ __forceinline__ uint32_t pack2_hi(float a, float b, float& la, float& lb) {
    __nv_bfloat16 ha = __float2bfloat16_rn(a), hb = __float2bfloat16_rn(b);
    la = a - __bfloat162float(ha);
    lb = b - __bfloat162float(hb);
    return (uint32_t)__bfloat16_as_ushort(ha) | ((uint32_t)__bfloat16_as_ushort(hb) << 16);
}
__device__ __forceinline__ uint32_t pack2(float a, float b) {
    __nv_bfloat16 ha = __float2bfloat16_rn(a), hb = __float2bfloat16_rn(b);
    return (uint32_t)__bfloat16_as_ushort(ha) | ((uint32_t)__bfloat16_as_ushort(hb) << 16);
}
__device__ __forceinline__ float2 unpack2(uint32_t u) {
    __nv_bfloat162 v = *reinterpret_cast<__nv_bfloat162*>(&u);
    return make_float2(__bfloat162float(v.x), __bfloat162float(v.y));
}
__device__ __forceinline__ void mma_bf16(float* c, uint32_t a0, uint32_t a1,
                                         uint32_t a2, uint32_t a3,
                                         uint32_t b0, uint32_t b1) {
    asm volatile(
        "mma.sync.aligned.m16n8k16.row.col.f32.bf16.bf16.f32 "
        "{%0,%1,%2,%3}, {%4,%5,%6,%7}, {%8,%9}, {%0,%1,%2,%3};"
        : "+f"(c[0]), "+f"(c[1]), "+f"(c[2]), "+f"(c[3])
        : "r"(a0), "r"(a1), "r"(a2), "r"(a3), "r"(b0), "r"(b1));
}
__device__ __forceinline__ void ldsm4(uint32_t& r0, uint32_t& r1, uint32_t& r2,
                                      uint32_t& r3, uint32_t addr) {
    asm volatile("ldmatrix.sync.aligned.m8n8.x4.shared.b16 {%0,%1,%2,%3}, [%4];"
                 : "=r"(r0), "=r"(r1), "=r"(r2), "=r"(r3) : "r"(addr));
}
__device__ __forceinline__ void cpa16(uint32_t dst, const void* src) {
    asm volatile("cp.async.cg.shared.global [%0], [%1], 16;" :: "r"(dst), "l"(src));
}
#define CP_COMMIT() asm volatile("cp.async.commit_group;" ::: "memory")
#define CP_WAIT0()  asm volatile("cp.async.wait_group 0;" ::: "memory")
#define CP_WAIT1()  asm volatile("cp.async.wait_group 1;" ::: "memory")

// tile geometry: 128 rows x 32 bf16 cols, row stride 80 bytes (conflict-free ldsm)
#define TW 80
#define TT (128 * TW)                   // 10240 per tile
#define BUFB (4 * TT)                   // 40960 per 4-tile buffer
#define STASHW 132
#define DYN_QK (2 * BUFB)               // 81920 (stash 67584 + red2 aliases)
#define DYN_PV (2 * BUFB + 512)         // 82432

// ---------------------------------------------------------------------------
// prep: split fp32 rows of Q and K into hi/lo bf16 (row-major, linear)
// ---------------------------------------------------------------------------
__global__ __launch_bounds__(256) void prep_qk_kernel(const float* __restrict__ Q,
                                                      const float* __restrict__ K) {
    const float* src = blockIdx.y ? K : Q;
    __nv_bfloat16* dh = blockIdx.y ? g_Kh : g_Qh;
    __nv_bfloat16* dl = blockIdx.y ? g_Kl : g_Ql;
    size_t idx = (size_t)blockIdx.x * 256 + threadIdx.x;
    const float* p = src + idx * 8;
    float4 f0 = *(const float4*)p, f1 = *(const float4*)(p + 4);
    float l[8];
    uint4 hv, lv;
    hv.x = pack2_hi(f0.x, f0.y, l[0], l[1]);
    hv.y = pack2_hi(f0.z, f0.w, l[2], l[3]);
    hv.z = pack2_hi(f1.x, f1.y, l[4], l[5]);
    hv.w = pack2_hi(f1.z, f1.w, l[6], l[7]);
    lv.x = pack2(l[0], l[1]); lv.y = pack2(l[2], l[3]);
    lv.z = pack2(l[4], l[5]); lv.w = pack2(l[6], l[7]);
    *(uint4*)(dh + idx * 8) = hv;
    *(uint4*)(dl + idx * 8) = lv;
}

__global__ __launch_bounds__(256) void prep_vt_kernel(const float* __restrict__ V) {
    int chunk = blockIdx.x, b = blockIdx.y, tid = threadIdx.x;
#pragma unroll
    for (int g = 0; g < 8; g++) {
        int item = tid + g * 256;
        int r = item & 127;           // n (dv)
        int c8 = item >> 7;           // k-group
        int k0 = chunk * 128 + c8 * 8;
        float f[8], l[8];
#pragma unroll
        for (int j = 0; j < 8; j++)
            f[j] = V[((size_t)b * SKL + k0 + j) * DD + r];
        uint4 hv, lv;
        hv.x = pack2_hi(f[0], f[1], l[0], l[1]);
        hv.y = pack2_hi(f[2], f[3], l[2], l[3]);
        hv.z = pack2_hi(f[4], f[5], l[4], l[5]);
        hv.w = pack2_hi(f[6], f[7], l[6], l[7]);
        lv.x = pack2(l[0], l[1]); lv.y = pack2(l[2], l[3]);
        lv.z = pack2(l[4], l[5]); lv.w = pack2(l[6], l[7]);
        size_t dst = ((size_t)b * DD + r) * SKL + k0;
        *(uint4*)(g_Vth + dst) = hv;
        *(uint4*)(g_Vtl + dst) = lv;
    }
}

// ---------------------------------------------------------------------------
// qk: E = exp(scale * Q @ K^T) masked (->0); writes split-bf16 Ehi/Elo +
// per-(row,ktile) partial sums. Pipelined 32-col slices.
// grid (16 kt, 16 qt, 16 b), 256 thr, 2 CTA/SM.
// ---------------------------------------------------------------------------
__global__ __launch_bounds__(256, 2) void qk_mma_kernel(const int* __restrict__ mask,
                                                        float* __restrict__ dummy) {
    extern __shared__ char sm[];
    const uint32_t sb = (uint32_t)__cvta_generic_to_shared(sm);
    const int tid = threadIdx.x, wid = tid >> 5, lane = tid & 31;
    const int wm = wid >> 2, wn = wid & 3;
    const int kt = blockIdx.x, qt = blockIdx.y, b = blockIdx.z;
    const size_t rowbase = (size_t)b * SQL + qt * 128;

    const int la_row = lane & 15;
    const int la_k   = (lane & 16) ? 16 : 0;
    const int lb_row = (lane & 7) + ((lane & 16) ? 8 : 0);
    const int lb_k   = (lane & 8) ? 16 : 0;

    float acc[4][4][4];
#pragma unroll
    for (int mt = 0; mt < 4; mt++)
#pragma unroll
        for (int nt = 0; nt < 4; nt++)
#pragma unroll
            for (int i = 0; i < 4; i++) acc[mt][nt][i] = 0.0f;

    const __nv_bfloat16* srcs[4] = {
        g_Qh + rowbase * DD, g_Ql + rowbase * DD,
        g_Kh + ((size_t)b * SKL + kt * 128) * DD,
        g_Kl + ((size_t)b * SKL + kt * 128) * DD};

    auto qstage = [&](int sl, int st) {
        uint32_t base = sb + (uint32_t)st * BUFB;
#pragma unroll
        for (int t = 0; t < 4; t++) {
            const __nv_bfloat16* sp = srcs[t] + sl * 32;
            uint32_t db = base + t * TT;
#pragma unroll
            for (int g = 0; g < 2; g++) {
                int idx = tid + g * 256;
                int row = idx >> 2, c = idx & 3;
                cpa16(db + row * TW + c * 16, sp + (size_t)row * DD + c * 8);
            }
        }
        CP_COMMIT();
    };

    qstage(0, 0);
#pragma unroll
    for (int sl = 0; sl < 4; sl++) {
        if (sl < 3) { qstage(sl + 1, (sl + 1) & 1); CP_WAIT1(); }
        else        { CP_WAIT0(); }
        __syncthreads();
        const uint32_t base = sb + (uint32_t)(sl & 1) * BUFB;
#pragma unroll
        for (int ks = 0; ks < 2; ks++) {
            const int kb = ks * 32;
            uint32_t bh[4][2], bl[4][2];
#pragma unroll
            for (int ntp = 0; ntp < 2; ntp++) {
                uint32_t ba = base + 2 * TT + (uint32_t)(wn * 32 + ntp * 16 + lb_row) * TW + kb + lb_k;
                ldsm4(bh[2 * ntp][0], bh[2 * ntp][1], bh[2 * ntp + 1][0], bh[2 * ntp + 1][1], ba);
                ldsm4(bl[2 * ntp][0], bl[2 * ntp][1], bl[2 * ntp + 1][0], bl[2 * ntp + 1][1], ba + TT);
            }
#pragma unroll
            for (int mt = 0; mt < 4; mt++) {
                uint32_t aa = base + (uint32_t)(wm * 64 + mt * 16 + la_row) * TW + kb + la_k;
                uint32_t ah0, ah1, ah2, ah3, al0, al1, al2, al3;
                ldsm4(ah0, ah1, ah2, ah3, aa);
                ldsm4(al0, al1, al2, al3, aa + TT);
#pragma unroll
                for (int nt = 0; nt < 4; nt++) {
                    mma_bf16(acc[mt][nt], ah0, ah1, ah2, ah3, bh[nt][0], bh[nt][1]);
                    mma_bf16(acc[mt][nt], al0, al1, al2, al3, bh[nt][0], bh[nt][1]);
                    mma_bf16(acc[mt][nt], ah0, ah1, ah2, ah3, bl[nt][0], bl[nt][1]);
                }
            }
        }
        __syncthreads();
    }

    // epilogue: mask (direct), exp, partial sums, stash, split-bf16 write
    float* stashf = (float*)sm;
    float* red2   = (float*)(sm + 128 * STASHW * 4);   // 67584

    const float scale = 0.08838834764831845f;
    const int rq = lane >> 2, qq = (lane & 3) * 2;
#pragma unroll
    for (int mt = 0; mt < 4; mt++) {
        const int rl1 = wm * 64 + mt * 16 + rq, rl2 = rl1 + 8;
        const size_t r1 = rowbase + rl1;
        float s1 = 0.0f, s2 = 0.0f;
#pragma unroll
        for (int nt = 0; nt < 4; nt++) {
            int cl = wn * 32 + nt * 8 + qq;
            int colg = kt * 128 + cl;
            int2 m1 = *(const int2*)(mask + r1 * SKL + colg);
            int2 m2 = *(const int2*)(mask + (r1 + 8) * SKL + colg);
            float* c = acc[mt][nt];
            float e0 = m1.x ? __expf(c[0] * scale) : 0.0f;
            float e1 = m1.y ? __expf(c[1] * scale) : 0.0f;
            float e2 = m2.x ? __expf(c[2] * scale) : 0.0f;
            float e3 = m2.y ? __expf(c[3] * scale) : 0.0f;
            stashf[rl1 * STASHW + cl]     = e0;
            stashf[rl1 * STASHW + cl + 1] = e1;
            stashf[rl2 * STASHW + cl]     = e2;
            stashf[rl2 * STASHW + cl + 1] = e3;
            s1 += e0 + e1;
            s2 += e2 + e3;
        }
#pragma unroll
        for (int off = 1; off <= 2; off <<= 1) {
            s1 += __shfl_xor_sync(0xffffffffu, s1, off);
            s2 += __shfl_xor_sync(0xffffffffu, s2, off);
        }
        if ((lane & 3) == 0) {
            red2[wn * 128 + rl1] = s1;
            red2[wn * 128 + rl2] = s2;
        }
    }
    __syncthreads();
    if (tid < 128) {
        float s = red2[tid] + red2[128 + tid] + red2[256 + tid] + red2[384 + tid];
        g_ps[(rowbase + tid) * NTILES + kt] = s;
    }

    // coalesced split write: Ehi/Elo bf16
#pragma unroll
    for (int g = 0; g < 16; g++) {
        int idx = tid + g * 256;
        int r = idx >> 5, cg = idx & 31;
        float4 e = *(const float4*)&stashf[r * STASHW + cg * 4];
        float l0, l1, l2, l3;
        uint32_t h0 = pack2_hi(e.x, e.y, l0, l1);
        uint32_t h1 = pack2_hi(e.z, e.w, l2, l3);
        size_t off = (rowbase + r) * SKL + kt * 128 + cg * 4;
        *(uint2*)(g_Eh + off) = make_uint2(h0, h1);
        *(uint2*)(g_El + off) = make_uint2(pack2(l0, l1), pack2(l2, l3));
    }
}

// ---------------------------------------------------------------------------
// pv: ctx = (E @ V) * inv; P = (Ehi+Elo) * inv written coalesced (final attn).
// 128 threads / 4 warps; each warp owns m32 x n128 so B fragments amortize
// over 2 m16 blocks (96 MMA per 20 LDSM per k16). Double-buffered slices.
// grid (16 qt, 16 b), 2 CTA/SM.
// ---------------------------------------------------------------------------
__global__ __launch_bounds__(128, 2) void pv_mma_kernel(float* __restrict__ attn,
                                                        float* __restrict__ ctx) {
    extern __shared__ char sm[];
    const uint32_t sb = (uint32_t)__cvta_generic_to_shared(sm);
    const int tid = threadIdx.x, w = tid >> 5, lane = tid & 31;
    const int rq = lane >> 2, qq = (lane & 3) * 2;
    const int qt = blockIdx.x, b = blockIdx.y;
    const size_t rowbase = (size_t)b * SQL + qt * 128;

    const int la_row = lane & 15;
    const int la_k   = (lane & 16) ? 16 : 0;
    const int lb_row = (lane & 7) + ((lane & 16) ? 8 : 0);
    const int lb_k   = (lane & 8) ? 16 : 0;

    float* sInv = (float*)(sm + 2 * BUFB);
    {
        const float* p = g_ps + (rowbase + tid) * NTILES;
        float s = 0.0f;
#pragma unroll
        for (int i = 0; i < 4; i++) {
            float4 v = *(const float4*)(p + i * 4);
            s += v.x + v.y + v.z + v.w;
        }
        sInv[tid] = 1.0f / s;
    }

    // acc[mb][nt][4]: warp rows w*32 + mb*16
    float acc[2][16][4];
#pragma unroll
    for (int mb = 0; mb < 2; mb++)
#pragma unroll
        for (int nt = 0; nt < 16; nt++)
#pragma unroll
            for (int i = 0; i < 4; i++) acc[mb][nt][i] = 0.0f;

    const __nv_bfloat16* vth = g_Vth + (size_t)b * DD * SKL;
    const __nv_bfloat16* vtl = g_Vtl + (size_t)b * DD * SKL;
    const __nv_bfloat16* eh = g_Eh + rowbase * SKL;
    const __nv_bfloat16* el = g_El + rowbase * SKL;

    // buffer layout per st: Eh(TT) El(TT) Vh(TT) Vl(TT); 512 chunks per tile
    auto stage = [&](int s, int st) {
        uint32_t base = sb + (uint32_t)st * BUFB;
#pragma unroll
        for (int g = 0; g < 4; g++) {
            int idx = tid + g * 128;
            int row = idx >> 2, c = idx & 3;
            size_t off = (size_t)row * SKL + s * 32 + c * 8;
            cpa16(base + row * TW + c * 16, eh + off);
            cpa16(base + TT + row * TW + c * 16, el + off);
            cpa16(base + 2 * TT + row * TW + c * 16, vth + off);
            cpa16(base + 3 * TT + row * TW + c * 16, vtl + off);
        }
        CP_COMMIT();
    };

    stage(0, 0);
    for (int s = 0; s < 64; s++) {
        if (s < 63) { stage(s + 1, (s + 1) & 1); CP_WAIT1(); }
        else        { CP_WAIT0(); }
        __syncthreads();

        const uint32_t base = sb + (uint32_t)(s & 1) * BUFB;
#pragma unroll
        for (int ks = 0; ks < 2; ks++) {
            const int kb = ks * 32;
            uint32_t ah[2][4], al[2][4];
#pragma unroll
            for (int mb = 0; mb < 2; mb++) {
                uint32_t aa = base + (uint32_t)(w * 32 + mb * 16 + la_row) * TW + kb + la_k;
                ldsm4(ah[mb][0], ah[mb][1], ah[mb][2], ah[mb][3], aa);
                ldsm4(al[mb][0], al[mb][1], al[mb][2], al[mb][3], aa + TT);
            }
#pragma unroll
            for (int ntp = 0; ntp < 8; ntp++) {
                uint32_t ba = base + 2 * TT + (uint32_t)(ntp * 16 + lb_row) * TW + kb + lb_k;
                uint32_t bh0, bh1, bh2, bh3, bl0, bl1, bl2, bl3;
                ldsm4(bh0, bh1, bh2, bh3, ba);
                ldsm4(bl0, bl1, bl2, bl3, ba + TT);
#pragma unroll
                for (int mb = 0; mb < 2; mb++) {
                    mma_bf16(acc[mb][2 * ntp], ah[mb][0], ah[mb][1], ah[mb][2], ah[mb][3], bh0, bh1);
                    mma_bf16(acc[mb][2 * ntp], al[mb][0], al[mb][1], al[mb][2], al[mb][3], bh0, bh1);
                    mma_bf16(acc[mb][2 * ntp], ah[mb][0], ah[mb][1], ah[mb][2], ah[mb][3], bl0, bl1);
                    mma_bf16(acc[mb][2 * ntp + 1], ah[mb][0], ah[mb][1], ah[mb][2], ah[mb][3], bh2, bh3);
                    mma_bf16(acc[mb][2 * ntp + 1], al[mb][0], al[mb][1], al[mb][2], al[mb][3], bh2, bh3);
                    mma_bf16(acc[mb][2 * ntp + 1], ah[mb][0], ah[mb][1], ah[mb][2], ah[mb][3], bl2, bl3);
                }
            }
        }

        // coalesced P write: P = (hi + lo) * inv_row
        const char* ebp = sm + (s & 1) * BUFB;
#pragma unroll
        for (int g = 0; g < 8; g++) {
            int idx = tid + g * 128;
            int row = idx >> 3, c4 = idx & 7;
            uint2 h = *(const uint2*)(ebp + row * TW + c4 * 8);
            uint2 l = *(const uint2*)(ebp + TT + row * TW + c4 * 8);
            float2 h0 = unpack2(h.x), h1 = unpack2(h.y);
            float2 l0 = unpack2(l.x), l1 = unpack2(l.y);
            float iv = sInv[row];
            float4 pv;
            pv.x = (h0.x + l0.x) * iv;
            pv.y = (h0.y + l0.y) * iv;
            pv.z = (h1.x + l1.x) * iv;
            pv.w = (h1.y + l1.y) * iv;
            *(float4*)(attn + (rowbase + row) * SKL + s * 32 + c4 * 4) = pv;
        }
        __syncthreads();
    }

    // ctx = acc * inv
#pragma unroll
    for (int mb = 0; mb < 2; mb++) {
        const size_t grow1 = rowbase + w * 32 + mb * 16 + rq;
        const size_t grow2 = grow1 + 8;
        const float inv1 = sInv[w * 32 + mb * 16 + rq];
        const float inv2 = sInv[w * 32 + mb * 16 + rq + 8];
#pragma unroll
        for (int nt = 0; nt < 16; nt++) {
            int cg = nt * 8 + qq;
            *(float2*)(ctx + grow1 * DD + cg) =
                make_float2(acc[mb][nt][0] * inv1, acc[mb][nt][1] * inv1);
            *(float2*)(ctx + grow2 * DD + cg) =
                make_float2(acc[mb][nt][2] * inv2, acc[mb][nt][3] * inv2);
        }
    }
}

// ---------------------------------------------------------------------------
extern "C" void kernel_launch(void* const* d_in, const int* in_sizes, int n_in,
                              void* d_out, int out_size) {
    const float* Q    = (const float*)d_in[0];
    const float* K    = (const float*)d_in[1];
    const float* V    = (const float*)d_in[2];
    const int*   mask = (const int*)d_in[3];

    float* ctx  = (float*)d_out;
    float* attn = (float*)d_out + (size_t)BB * SQL * DD;

    static bool attr_done = false;
    if (!attr_done) {
        cudaFuncSetAttribute(qk_mma_kernel, cudaFuncAttributeMaxDynamicSharedMemorySize, DYN_QK);
        cudaFuncSetAttribute(pv_mma_kernel, cudaFuncAttributeMaxDynamicSharedMemorySize, DYN_PV);
        attr_done = true;
    }

    prep_qk_kernel<<<dim3(2048, 2), 256>>>(Q, K);
    prep_vt_kernel<<<dim3(16, BB), 256>>>(V);
    qk_mma_kernel<<<dim3(16, 16, BB), 256, DYN_QK>>>(mask, attn);
    pv_mma_kernel<<<dim3(16, BB), 128, DYN_PV>>>(attn, ctx);
}

// round 12
// speedup vs baseline: 1.3945x; 1.0854x over previous
#include <cuda_runtime.h>
#include <cuda_bf16.h>
#include <cuda_fp16.h>
#include <cstdint>
#include <math.h>

#define BB   16
#define SQL  2048
#define SKL  2048
#define DD   128
#define NROWS (BB * SQL)
#define NTILES 16

// ---------------- scratch (__device__ globals; no allocation) ----------------
__device__ __nv_bfloat16 g_Qh[(size_t)BB * SQL * DD];
__device__ __nv_bfloat16 g_Ql[(size_t)BB * SQL * DD];
__device__ __nv_bfloat16 g_Kh[(size_t)BB * SKL * DD];
__device__ __nv_bfloat16 g_Kl[(size_t)BB * SKL * DD];
__device__ __half g_Vth[(size_t)BB * DD * SKL];          // V^T hi (fp16)
__device__ __half g_Vtl[(size_t)BB * DD * SKL];          // V^T lo (fp16)
__device__ __half g_Ef[(size_t)NROWS * SKL];             // exp (fp16)
__device__ float g_ps[(size_t)NROWS * NTILES];           // per-(row,ktile) sum exp

// ---------------- helpers ----------------------------------------------------
__device__ __forceinline__ uint32_t pack2_hi(float a, float b, float& la, float& lb) {
    __nv_bfloat16 ha = __float2bfloat16_rn(a), hb = __float2bfloat16_rn(b);
    la = a - __bfloat162float(ha);
    lb = b - __bfloat162float(hb);
    return (uint32_t)__bfloat16_as_ushort(ha) | ((uint32_t)__bfloat16_as_ushort(hb) << 16);
}
__device__ __forceinline__ uint32_t pack2(float a, float b) {
    __nv_bfloat16 ha = __float2bfloat16_rn(a), hb = __float2bfloat16_rn(b);
    return (uint32_t)__bfloat16_as_ushort(ha) | ((uint32_t)__bfloat16_as_ushort(hb) << 16);
}
__device__ __forceinline__ uint32_t pack2h_hi(float a, float b, float& la, float& lb) {
    __half ha = __float2half_rn(a), hb = __float2half_rn(b);
    la = a - __half2float(ha);
    lb = b - __half2float(hb);
    return (uint32_t)__half_as_ushort(ha) | ((uint32_t)__half_as_ushort(hb) << 16);
}
__device__ __forceinline__ uint32_t pack2h(float a, float b) {
    __half ha = __float2half_rn(a), hb = __float2half_rn(b);
    return (uint32_t)__half_as_ushort(ha) | ((uint32_t)__half_as_ushort(hb) << 16);
}
__device__ __forceinline__ float2 unpack2h(uint32_t u) {
    __half2 v = *reinterpret_cast<__half2*>(&u);
    return make_float2(__half2float(v.x), __half2float(v.y));
}
__device__ __forceinline__ void mma_bf16(float* c, uint32_t a0, uint32_t a1,
                                         uint32_t a2, uint32_t a3,
                                         uint32_t b0, uint32_t b1) {
    asm volatile(
        "mma.sync.aligned.m16n8k16.row.col.f32.bf16.bf16.f32 "
        "{%0,%1,%2,%3}, {%4,%5,%6,%7}, {%8,%9}, {%0,%1,%2,%3};"
        : "+f"(c[0]), "+f"(c[1]), "+f"(c[2]), "+f"(c[3])
        : "r"(a0), "r"(a1), "r"(a2), "r"(a3), "r"(b0), "r"(b1));
}
__device__ __forceinline__ void mma_f16(float* c, uint32_t a0, uint32_t a1,
                                        uint32_t a2, uint32_t a3,
                                        uint32_t b0, uint32_t b1) {
    asm volatile(
        "mma.sync.aligned.m16n8k16.row.col.f32.f16.f16.f32 "
        "{%0,%1,%2,%3}, {%4,%5,%6,%7}, {%8,%9}, {%0,%1,%2,%3};"
        : "+f"(c[0]), "+f"(c[1]), "+f"(c[2]), "+f"(c[3])
        : "r"(a0), "r"(a1), "r"(a2), "r"(a3), "r"(b0), "r"(b1));
}
__device__ __forceinline__ void ldsm4(uint32_t& r0, uint32_t& r1, uint32_t& r2,
                                      uint32_t& r3, uint32_t addr) {
    asm volatile("ldmatrix.sync.aligned.m8n8.x4.shared.b16 {%0,%1,%2,%3}, [%4];"
                 : "=r"(r0), "=r"(r1), "=r"(r2), "=r"(r3) : "r"(addr));
}
__device__ __forceinline__ void cpa16(uint32_t dst, const void* src) {
    asm volatile("cp.async.cg.shared.global [%0], [%1], 16;" :: "r"(dst), "l"(src));
}
#define CP_COMMIT() asm volatile("cp.async.commit_group;" ::: "memory")
#define CP_WAIT0()  asm volatile("cp.async.wait_group 0;" ::: "memory")
#define CP_WAIT1()  asm volatile("cp.async.wait_group 1;" ::: "memory")

// tile geometry: 128 rows x 32 cols (2B elems), row stride 80 bytes
#define TW 80
#define TT (128 * TW)                   // 10240 per tile
#define BUFB (4 * TT)                   // qk: 4-tile buffer
#define BUFB3 (3 * TT)                  // pv: 3-tile buffer (E, Vh, Vl)
#define STASHW 132
#define DYN_QK (2 * BUFB)               // 81920
#define DYN_PV (2 * BUFB3 + 512)        // 61952

// ---------------------------------------------------------------------------
// prep: split fp32 rows of Q and K into hi/lo bf16 (row-major, linear)
// ---------------------------------------------------------------------------
__global__ __launch_bounds__(256) void prep_qk_kernel(const float* __restrict__ Q,
                                                      const float* __restrict__ K) {
    const float* src = blockIdx.y ? K : Q;
    __nv_bfloat16* dh = blockIdx.y ? g_Kh : g_Qh;
    __nv_bfloat16* dl = blockIdx.y ? g_Kl : g_Ql;
    size_t idx = (size_t)blockIdx.x * 256 + threadIdx.x;
    const float* p = src + idx * 8;
    float4 f0 = *(const float4*)p, f1 = *(const float4*)(p + 4);
    float l[8];
    uint4 hv, lv;
    hv.x = pack2_hi(f0.x, f0.y, l[0], l[1]);
    hv.y = pack2_hi(f0.z, f0.w, l[2], l[3]);
    hv.z = pack2_hi(f1.x, f1.y, l[4], l[5]);
    hv.w = pack2_hi(f1.z, f1.w, l[6], l[7]);
    lv.x = pack2(l[0], l[1]); lv.y = pack2(l[2], l[3]);
    lv.z = pack2(l[4], l[5]); lv.w = pack2(l[6], l[7]);
    *(uint4*)(dh + idx * 8) = hv;
    *(uint4*)(dl + idx * 8) = lv;
}

// prep: V^T fp16 hi/lo: [b][dv][k]
__global__ __launch_bounds__(256) void prep_vt_kernel(const float* __restrict__ V) {
    int chunk = blockIdx.x, b = blockIdx.y, tid = threadIdx.x;
#pragma unroll
    for (int g = 0; g < 8; g++) {
        int item = tid + g * 256;
        int r = item & 127;           // n (dv)
        int c8 = item >> 7;           // k-group
        int k0 = chunk * 128 + c8 * 8;
        float f[8], l[8];
#pragma unroll
        for (int j = 0; j < 8; j++)
            f[j] = V[((size_t)b * SKL + k0 + j) * DD + r];
        uint4 hv, lv;
        hv.x = pack2h_hi(f[0], f[1], l[0], l[1]);
        hv.y = pack2h_hi(f[2], f[3], l[2], l[3]);
        hv.z = pack2h_hi(f[4], f[5], l[4], l[5]);
        hv.w = pack2h_hi(f[6], f[7], l[6], l[7]);
        lv.x = pack2h(l[0], l[1]); lv.y = pack2h(l[2], l[3]);
        lv.z = pack2h(l[4], l[5]); lv.w = pack2h(l[6], l[7]);
        size_t dst = ((size_t)b * DD + r) * SKL + k0;
        *(uint4*)(g_Vth + dst) = hv;
        *(uint4*)(g_Vtl + dst) = lv;
    }
}

// ---------------------------------------------------------------------------
// qk: E = exp(scale * Q @ K^T) masked (->0), quantized to fp16; writes E +
// per-(row,ktile) sums of the QUANTIZED values. grid (16,16,16), 256 thr.
// ---------------------------------------------------------------------------
__global__ __launch_bounds__(256, 2) void qk_mma_kernel(const int* __restrict__ mask,
                                                        float* __restrict__ dummy) {
    extern __shared__ char sm[];
    const uint32_t sb = (uint32_t)__cvta_generic_to_shared(sm);
    const int tid = threadIdx.x, wid = tid >> 5, lane = tid & 31;
    const int wm = wid >> 2, wn = wid & 3;
    const int kt = blockIdx.x, qt = blockIdx.y, b = blockIdx.z;
    const size_t rowbase = (size_t)b * SQL + qt * 128;

    const int la_row = lane & 15;
    const int la_k   = (lane & 16) ? 16 : 0;
    const int lb_row = (lane & 7) + ((lane & 16) ? 8 : 0);
    const int lb_k   = (lane & 8) ? 16 : 0;

    float acc[4][4][4];
#pragma unroll
    for (int mt = 0; mt < 4; mt++)
#pragma unroll
        for (int nt = 0; nt < 4; nt++)
#pragma unroll
            for (int i = 0; i < 4; i++) acc[mt][nt][i] = 0.0f;

    const __nv_bfloat16* srcs[4] = {
        g_Qh + rowbase * DD, g_Ql + rowbase * DD,
        g_Kh + ((size_t)b * SKL + kt * 128) * DD,
        g_Kl + ((size_t)b * SKL + kt * 128) * DD};

    auto qstage = [&](int sl, int st) {
        uint32_t base = sb + (uint32_t)st * BUFB;
#pragma unroll
        for (int t = 0; t < 4; t++) {
            const __nv_bfloat16* sp = srcs[t] + sl * 32;
            uint32_t db = base + t * TT;
#pragma unroll
            for (int g = 0; g < 2; g++) {
                int idx = tid + g * 256;
                int row = idx >> 2, c = idx & 3;
                cpa16(db + row * TW + c * 16, sp + (size_t)row * DD + c * 8);
            }
        }
        CP_COMMIT();
    };

    qstage(0, 0);
#pragma unroll
    for (int sl = 0; sl < 4; sl++) {
        if (sl < 3) { qstage(sl + 1, (sl + 1) & 1); CP_WAIT1(); }
        else        { CP_WAIT0(); }
        __syncthreads();
        const uint32_t base = sb + (uint32_t)(sl & 1) * BUFB;
#pragma unroll
        for (int ks = 0; ks < 2; ks++) {
            const int kb = ks * 32;
            uint32_t bh[4][2], bl[4][2];
#pragma unroll
            for (int ntp = 0; ntp < 2; ntp++) {
                uint32_t ba = base + 2 * TT + (uint32_t)(wn * 32 + ntp * 16 + lb_row) * TW + kb + lb_k;
                ldsm4(bh[2 * ntp][0], bh[2 * ntp][1], bh[2 * ntp + 1][0], bh[2 * ntp + 1][1], ba);
                ldsm4(bl[2 * ntp][0], bl[2 * ntp][1], bl[2 * ntp + 1][0], bl[2 * ntp + 1][1], ba + TT);
            }
#pragma unroll
            for (int mt = 0; mt < 4; mt++) {
                uint32_t aa = base + (uint32_t)(wm * 64 + mt * 16 + la_row) * TW + kb + la_k;
                uint32_t ah0, ah1, ah2, ah3, al0, al1, al2, al3;
                ldsm4(ah0, ah1, ah2, ah3, aa);
                ldsm4(al0, al1, al2, al3, aa + TT);
#pragma unroll
                for (int nt = 0; nt < 4; nt++) {
                    mma_bf16(acc[mt][nt], ah0, ah1, ah2, ah3, bh[nt][0], bh[nt][1]);
                    mma_bf16(acc[mt][nt], al0, al1, al2, al3, bh[nt][0], bh[nt][1]);
                    mma_bf16(acc[mt][nt], ah0, ah1, ah2, ah3, bl[nt][0], bl[nt][1]);
                }
            }
        }
        __syncthreads();
    }

    // epilogue: mask (direct), exp, fp16 quantize, sums, stash, fp16 write
    float* stashf = (float*)sm;
    float* red2   = (float*)(sm + 128 * STASHW * 4);   // 67584

    const float scale = 0.08838834764831845f;
    const int rq = lane >> 2, qq = (lane & 3) * 2;
#pragma unroll
    for (int mt = 0; mt < 4; mt++) {
        const int rl1 = wm * 64 + mt * 16 + rq, rl2 = rl1 + 8;
        const size_t r1 = rowbase + rl1;
        float s1 = 0.0f, s2 = 0.0f;
#pragma unroll
        for (int nt = 0; nt < 4; nt++) {
            int cl = wn * 32 + nt * 8 + qq;
            int colg = kt * 128 + cl;
            int2 m1 = *(const int2*)(mask + r1 * SKL + colg);
            int2 m2 = *(const int2*)(mask + (r1 + 8) * SKL + colg);
            float* c = acc[mt][nt];
            float e0 = m1.x ? __half2float(__float2half_rn(__expf(c[0] * scale))) : 0.0f;
            float e1 = m1.y ? __half2float(__float2half_rn(__expf(c[1] * scale))) : 0.0f;
            float e2 = m2.x ? __half2float(__float2half_rn(__expf(c[2] * scale))) : 0.0f;
            float e3 = m2.y ? __half2float(__float2half_rn(__expf(c[3] * scale))) : 0.0f;
            stashf[rl1 * STASHW + cl]     = e0;
            stashf[rl1 * STASHW + cl + 1] = e1;
            stashf[rl2 * STASHW + cl]     = e2;
            stashf[rl2 * STASHW + cl + 1] = e3;
            s1 += e0 + e1;
            s2 += e2 + e3;
        }
#pragma unroll
        for (int off = 1; off <= 2; off <<= 1) {
            s1 += __shfl_xor_sync(0xffffffffu, s1, off);
            s2 += __shfl_xor_sync(0xffffffffu, s2, off);
        }
        if ((lane & 3) == 0) {
            red2[wn * 128 + rl1] = s1;
            red2[wn * 128 + rl2] = s2;
        }
    }
    __syncthreads();
    if (tid < 128) {
        float s = red2[tid] + red2[128 + tid] + red2[256 + tid] + red2[384 + tid];
        g_ps[(rowbase + tid) * NTILES + kt] = s;
    }

    // coalesced fp16 E write
#pragma unroll
    for (int g = 0; g < 16; g++) {
        int idx = tid + g * 256;
        int r = idx >> 5, cg = idx & 31;
        float4 e = *(const float4*)&stashf[r * STASHW + cg * 4];
        size_t off = (rowbase + r) * SKL + kt * 128 + cg * 4;
        *(uint2*)(g_Ef + off) = make_uint2(pack2h(e.x, e.y), pack2h(e.z, e.w));
    }
}

// ---------------------------------------------------------------------------
// pv: ctx = (E @ (Vh+Vl)) * inv (2-term fp16); P = E * inv written coalesced
// (final attn). E/Vh/Vl staged via cp.async, double-buffered 32-k slices.
// grid (16 qt, 16 b), 256 thr / 8 warps (m16 each), 2 CTA/SM.
// ---------------------------------------------------------------------------
__global__ __launch_bounds__(256, 2) void pv_mma_kernel(float* __restrict__ attn,
                                                        float* __restrict__ ctx) {
    extern __shared__ char sm[];
    const uint32_t sb = (uint32_t)__cvta_generic_to_shared(sm);
    const int tid = threadIdx.x, w = tid >> 5, lane = tid & 31;
    const int rq = lane >> 2, qq = (lane & 3) * 2;
    const int qt = blockIdx.x, b = blockIdx.y;
    const size_t rowbase = (size_t)b * SQL + qt * 128;
    const size_t grow1 = rowbase + w * 16 + rq;
    const size_t grow2 = grow1 + 8;

    const int la_row = lane & 15;
    const int la_k   = (lane & 16) ? 16 : 0;
    const int lb_row = (lane & 7) + ((lane & 16) ? 8 : 0);
    const int lb_k   = (lane & 8) ? 16 : 0;

    float* sInv = (float*)(sm + 2 * BUFB3);
    if (tid < 128) {
        const float* p = g_ps + (rowbase + tid) * NTILES;
        float s = 0.0f;
#pragma unroll
        for (int i = 0; i < 4; i++) {
            float4 v = *(const float4*)(p + i * 4);
            s += v.x + v.y + v.z + v.w;
        }
        sInv[tid] = 1.0f / s;
    }

    float acc[16][4];
#pragma unroll
    for (int nt = 0; nt < 16; nt++)
#pragma unroll
        for (int i = 0; i < 4; i++) acc[nt][i] = 0.0f;

    const __half* vth = g_Vth + (size_t)b * DD * SKL;
    const __half* vtl = g_Vtl + (size_t)b * DD * SKL;
    const __half* ef  = g_Ef + rowbase * SKL;

    // buffer layout per st: E(TT) Vh(TT) Vl(TT)
    auto stage = [&](int s, int st) {
        uint32_t base = sb + (uint32_t)st * BUFB3;
#pragma unroll
        for (int g = 0; g < 2; g++) {
            int idx = tid + g * 256;
            int row = idx >> 2, c = idx & 3;
            size_t off = (size_t)row * SKL + s * 32 + c * 8;
            cpa16(base + row * TW + c * 16, ef + off);
            cpa16(base + TT + row * TW + c * 16, vth + off);
            cpa16(base + 2 * TT + row * TW + c * 16, vtl + off);
        }
        CP_COMMIT();
    };

    stage(0, 0);
    float inv1 = 0.0f, inv2 = 0.0f;
    for (int s = 0; s < 64; s++) {
        if (s < 63) { stage(s + 1, (s + 1) & 1); CP_WAIT1(); }
        else        { CP_WAIT0(); }
        __syncthreads();
        if (s == 0) { inv1 = sInv[w * 16 + rq]; inv2 = sInv[w * 16 + rq + 8]; }

        const uint32_t base = sb + (uint32_t)(s & 1) * BUFB3;
#pragma unroll
        for (int ks = 0; ks < 2; ks++) {
            const int kb = ks * 32;
            uint32_t aa = base + (uint32_t)(w * 16 + la_row) * TW + kb + la_k;
            uint32_t a0, a1, a2, a3;
            ldsm4(a0, a1, a2, a3, aa);
#pragma unroll
            for (int ntp = 0; ntp < 8; ntp++) {
                uint32_t ba = base + TT + (uint32_t)(ntp * 16 + lb_row) * TW + kb + lb_k;
                uint32_t bh0, bh1, bh2, bh3, bl0, bl1, bl2, bl3;
                ldsm4(bh0, bh1, bh2, bh3, ba);
                ldsm4(bl0, bl1, bl2, bl3, ba + TT);
                mma_f16(acc[2 * ntp],     a0, a1, a2, a3, bh0, bh1);
                mma_f16(acc[2 * ntp],     a0, a1, a2, a3, bl0, bl1);
                mma_f16(acc[2 * ntp + 1], a0, a1, a2, a3, bh2, bh3);
                mma_f16(acc[2 * ntp + 1], a0, a1, a2, a3, bl2, bl3);
            }
        }

        // coalesced P write: P = E * inv_row
        const char* ebp = sm + (s & 1) * BUFB3;
#pragma unroll
        for (int g = 0; g < 4; g++) {
            int idx = tid + g * 256;
            int row = idx >> 3, c4 = idx & 7;
            uint2 h = *(const uint2*)(ebp + row * TW + c4 * 8);
            float2 h0 = unpack2h(h.x), h1 = unpack2h(h.y);
            float iv = sInv[row];
            float4 pv;
            pv.x = h0.x * iv;
            pv.y = h0.y * iv;
            pv.z = h1.x * iv;
            pv.w = h1.y * iv;
            *(float4*)(attn + (rowbase + row) * SKL + s * 32 + c4 * 4) = pv;
        }
        __syncthreads();
    }

    // ctx = acc * inv
#pragma unroll
    for (int nt = 0; nt < 16; nt++) {
        int cg = nt * 8 + qq;
        *(float2*)(ctx + grow1 * DD + cg) =
            make_float2(acc[nt][0] * inv1, acc[nt][1] * inv1);
        *(float2*)(ctx + grow2 * DD + cg) =
            make_float2(acc[nt][2] * inv2, acc[nt][3] * inv2);
    }
}

// ---------------------------------------------------------------------------
extern "C" void kernel_launch(void* const* d_in, const int* in_sizes, int n_in,
                              void* d_out, int out_size) {
    const float* Q    = (const float*)d_in[0];
    const float* K    = (const float*)d_in[1];
    const float* V    = (const float*)d_in[2];
    const int*   mask = (const int*)d_in[3];

    float* ctx  = (float*)d_out;
    float* attn = (float*)d_out + (size_t)BB * SQL * DD;

    static bool attr_done = false;
    if (!attr_done) {
        cudaFuncSetAttribute(qk_mma_kernel, cudaFuncAttributeMaxDynamicSharedMemorySize, DYN_QK);
        cudaFuncSetAttribute(pv_mma_kernel, cudaFuncAttributeMaxDynamicSharedMemorySize, DYN_PV);
        attr_done = true;
    }

    prep_qk_kernel<<<dim3(2048, 2), 256>>>(Q, K);
    prep_vt_kernel<<<dim3(16, BB), 256>>>(V);
    qk_mma_kernel<<<dim3(16, 16, BB), 256, DYN_QK>>>(mask, attn);
    pv_mma_kernel<<<dim3(16, BB), 256, DYN_PV>>>(attn, ctx);
}